// round 13
// baseline (speedup 1.0000x reference)
#include <cuda_runtime.h>
#include <cuda_bf16.h>
#include <cuda_fp16.h>
#include <cstdint>
#include <math.h>

#define NN   100000
#define NE   1600000
#define NCAT 20
#define EMBD 32
#define CARD 100
#define NB_SCAN 98   // ceil(NN/1024)
#define C1ROWS 50048            // emb/W2 pipeline chunk 1 rows (multiple of 128)

// ---------------- scratch (device globals) ----------------
__device__ __half g_c[(size_t)NN * 64];           // x_cont fp16
__device__ __half g_p1[(size_t)NN * 128];         // layer buffers (fp16)
__device__ __half g_p2[(size_t)NN * 128];
__device__ __half g_y[(size_t)NN * 128];          // fp16 pre-aggregation features
__device__ float g_z[(size_t)NN * 128];
__device__ float g_agg[(size_t)NN * 128];
__device__ float g_s1[NN], g_s2[NN];
__device__ __half g_wt[768 * 128];                // [n][k] transposed fp16 weights
__device__ float g_bfl[128], g_bfr[128];          // folded conv1 biases
__device__ __half g_Th[NCAT * CARD * 128];        // fused emb@W1 tables (fp16)
// CSR
__device__ int g_cnt[NN];
__device__ int g_start[NN + 1];
__device__ int g_cursor[NN];
__device__ int g_csrc[NE];
__device__ int g_bsum[NB_SCAN];

__device__ __forceinline__ float gelu_f(float v) {
    return 0.5f * v * (1.0f + erff(v * 0.70710678118654752f));
}
__device__ __forceinline__ void mma_f16(float4& c, const uint32_t* a, const uint32_t* b) {
    asm volatile("mma.sync.aligned.m16n8k16.row.col.f32.f16.f16.f32 "
                 "{%0,%1,%2,%3}, {%4,%5,%6,%7}, {%8,%9}, {%0,%1,%2,%3};"
                 : "+f"(c.x), "+f"(c.y), "+f"(c.z), "+f"(c.w)
                 : "r"(a[0]), "r"(a[1]), "r"(a[2]), "r"(a[3]), "r"(b[0]), "r"(b[1]));
}
__device__ __forceinline__ void ldmx4(uint32_t& r0, uint32_t& r1, uint32_t& r2, uint32_t& r3,
                                      uint32_t addr) {
    asm volatile("ldmatrix.sync.aligned.m8n8.x4.shared.b16 {%0,%1,%2,%3}, [%4];"
                 : "=r"(r0), "=r"(r1), "=r"(r2), "=r"(r3) : "r"(addr));
}
__device__ __forceinline__ void cpasync16(uint32_t dst, const void* src) {
    asm volatile("cp.async.cg.shared.global [%0], [%1], 16;" :: "r"(dst), "l"(src));
}
__device__ __forceinline__ void cp_commit() { asm volatile("cp.async.commit_group;"); }
template<int N> __device__ __forceinline__ void cp_wait() {
    asm volatile("cp.async.wait_group %0;" :: "n"(N));
}
// 8B L2-only load (skip L1 — no reuse)
__device__ __forceinline__ uint2 ldcg8(const void* p) {
    uint2 v;
    asm volatile("ld.global.cg.v2.u32 {%0,%1}, [%2];" : "=r"(v.x), "=r"(v.y) : "l"(p));
    return v;
}

// ---------------- prep kernels ----------------
__global__ void prep_weight(const float* __restrict__ W, int K, __half* __restrict__ o) {
    int i = blockIdx.x * blockDim.x + threadIdx.x;
    if (i < 128 * K) {
        int k = i >> 7, n = i & 127;
        o[(size_t)n * K + k] = __float2half(W[i]);
    }
}
__global__ void __launch_bounds__(256)
fold_w3(const float* __restrict__ W3, const float* __restrict__ cW,
        const float* __restrict__ b3, const float* __restrict__ extra_bias,
        __half* __restrict__ o, float* __restrict__ obias) {
    int idx = blockIdx.x * 256 + threadIdx.x;
    int k = idx >> 7, n = idx & 127;
    float acc = 0.f;
    for (int d = 0; d < 128; d++)
        acc += W3[k * 128 + d] * cW[d * 128 + n];
    o[(size_t)n * 128 + k] = __float2half(acc);
    if (k == 0) {
        float bacc = extra_bias ? extra_bias[n] : 0.f;
        for (int d = 0; d < 128; d++) bacc += b3[d] * cW[d * 128 + n];
        obias[n] = bacc;
    }
}
__global__ void copy_cont_h(const float* __restrict__ xc) {
    int i = blockIdx.x * blockDim.x + threadIdx.x;
    if (i < NN * 32) {
        float2 v = *(const float2*)&xc[(size_t)i * 2];
        *(__half2*)&g_c[(size_t)i * 2] = __floats2half2_rn(v.x, v.y);
    }
}

// ---------------- emb@W1 table precompute ----------------
__global__ void __launch_bounds__(256)
prep_T(const float* __restrict__ emb, const float* __restrict__ W1) {
    __shared__ float se[50 * 32];
    __shared__ float sw[32 * 128];
    int c = blockIdx.x >> 1;
    int rh = blockIdx.x & 1;
    int tid = threadIdx.x;
    for (int i = tid; i < 50 * 32; i += 256)
        se[i] = emb[(size_t)c * CARD * EMBD + rh * 50 * 32 + i];
    for (int i = tid; i < 32 * 128; i += 256)
        sw[i] = W1[(size_t)(c * 32) * 128 + i];
    __syncthreads();
    for (int i = 0; i < 25; i++) {
        int idx = tid + i * 256;
        int r = idx >> 7, n = idx & 127;
        float acc = 0.f;
#pragma unroll
        for (int d = 0; d < 32; d++)
            acc += se[r * 32 + d] * sw[d * 128 + n];
        g_Th[((size_t)c * CARD + rh * 50 + r) * 128 + n] = __float2half(acc);
    }
}

// ---------------- MLP layer 1 via fp16 table lookup-sum (node range) ----------------
__global__ void __launch_bounds__(256)
emb_mlp1(const int* __restrict__ xcat, const float* __restrict__ b1,
         __half* __restrict__ o, int base, int count) {
    int w = base + ((blockIdx.x * blockDim.x + threadIdx.x) >> 5);
    if (w >= base + count || w >= NN) return;
    int lane = threadIdx.x & 31;
    const int* xc = xcat + (size_t)w * NCAT;
    float4 acc = *(const float4*)&b1[lane * 4];
#pragma unroll
    for (int c = 0; c < NCAT; c++) {
        int cat = __ldg(&xc[c]);
        uint2 u = *(const uint2*)&g_Th[((size_t)c * CARD + cat) * 128 + lane * 4];
        float2 f0 = __half22float2(*(__half2*)&u.x);
        float2 f1 = __half22float2(*(__half2*)&u.y);
        acc.x += f0.x; acc.y += f0.y; acc.z += f1.x; acc.w += f1.y;
    }
    __half2 o0 = __floats2half2_rn(gelu_f(acc.x), gelu_f(acc.y));
    __half2 o1 = __floats2half2_rn(gelu_f(acc.z), gelu_f(acc.w));
    size_t off = (size_t)w * 128 + lane * 4;
    *(__half2*)&o[off] = o0;
    *(__half2*)&o[off + 2] = o1;
}

// ---------------- CSR build ----------------
__global__ void zero_cnt() {
    int i = blockIdx.x * blockDim.x + threadIdx.x;
    if (i < NN) g_cnt[i] = 0;
}
__global__ void count_k(const int* __restrict__ ei, int E) {
    int e = blockIdx.x * blockDim.x + threadIdx.x;
    if (e < E) atomicAdd(&g_cnt[ei[E + e]], 1);
}
__global__ void scan_block() {
    __shared__ int sh[1024];
    int tid = threadIdx.x;
    int i = blockIdx.x * 1024 + tid;
    int v = (i < NN) ? g_cnt[i] : 0;
    sh[tid] = v;
    __syncthreads();
#pragma unroll
    for (int off = 1; off < 1024; off <<= 1) {
        int t = (tid >= off) ? sh[tid - off] : 0;
        __syncthreads();
        sh[tid] += t;
        __syncthreads();
    }
    if (i < NN) g_start[i] = sh[tid] - v;
    if (tid == 1023) g_bsum[blockIdx.x] = sh[1023];
}
__global__ void scan_top() {
    if (threadIdx.x == 0) {
        int acc = 0;
        for (int j = 0; j < NB_SCAN; j++) { int t = g_bsum[j]; g_bsum[j] = acc; acc += t; }
        g_start[NN] = acc;
    }
}
__global__ void scan_add() {
    int i = blockIdx.x * blockDim.x + threadIdx.x;
    if (i < NN) {
        int s = g_start[i] + g_bsum[i >> 10];
        g_start[i] = s;
        g_cursor[i] = s;
    }
}
__global__ void fill_k(const int* __restrict__ ei, int E) {
    int e = blockIdx.x * blockDim.x + threadIdx.x;
    if (e < E) {
        int dst = ei[E + e];
        int pos = atomicAdd(&g_cursor[dst], 1);
        g_csrc[pos] = ei[e];
    }
}

// ---------------- gather kernels ----------------
// warp per node, 4-edge unroll, L2-only loads
__global__ void gather_vec(const __half* __restrict__ y, float* __restrict__ agg) {
    int w = (blockIdx.x * blockDim.x + threadIdx.x) >> 5;
    if (w >= NN) return;
    int lane = threadIdx.x & 31;
    int s = g_start[w], e = g_start[w + 1];
    float inv = 1.f / fmaxf((float)(e - s), 1.f);
    float a0 = 0.f, a1 = 0.f, a2 = 0.f, a3 = 0.f;
    float b0 = 0.f, b1 = 0.f, b2 = 0.f, b3 = 0.f;
    float c0 = 0.f, c1 = 0.f, c2 = 0.f, c3 = 0.f;
    float d0 = 0.f, d1 = 0.f, d2 = 0.f, d3 = 0.f;
    int i = s;
    for (; i + 3 < e; i += 4) {
        int r0 = __ldg(&g_csrc[i]),     r1 = __ldg(&g_csrc[i + 1]);
        int r2 = __ldg(&g_csrc[i + 2]), r3 = __ldg(&g_csrc[i + 3]);
        uint2 u0 = ldcg8(&y[(size_t)r0 * 128 + lane * 4]);
        uint2 u1 = ldcg8(&y[(size_t)r1 * 128 + lane * 4]);
        uint2 u2 = ldcg8(&y[(size_t)r2 * 128 + lane * 4]);
        uint2 u3 = ldcg8(&y[(size_t)r3 * 128 + lane * 4]);
        float2 p0 = __half22float2(*(__half2*)&u0.x);
        float2 p1 = __half22float2(*(__half2*)&u0.y);
        float2 q0 = __half22float2(*(__half2*)&u1.x);
        float2 q1 = __half22float2(*(__half2*)&u1.y);
        float2 t0 = __half22float2(*(__half2*)&u2.x);
        float2 t1 = __half22float2(*(__half2*)&u2.y);
        float2 v0 = __half22float2(*(__half2*)&u3.x);
        float2 v1 = __half22float2(*(__half2*)&u3.y);
        a0 += p0.x; a1 += p0.y; a2 += p1.x; a3 += p1.y;
        b0 += q0.x; b1 += q0.y; b2 += q1.x; b3 += q1.y;
        c0 += t0.x; c1 += t0.y; c2 += t1.x; c3 += t1.y;
        d0 += v0.x; d1 += v0.y; d2 += v1.x; d3 += v1.y;
    }
    for (; i < e; i++) {
        int r0 = __ldg(&g_csrc[i]);
        uint2 u0 = ldcg8(&y[(size_t)r0 * 128 + lane * 4]);
        float2 p0 = __half22float2(*(__half2*)&u0.x);
        float2 p1 = __half22float2(*(__half2*)&u0.y);
        a0 += p0.x; a1 += p0.y; a2 += p1.x; a3 += p1.y;
    }
    float4 o = make_float4((a0 + b0 + c0 + d0) * inv, (a1 + b1 + c1 + d1) * inv,
                           (a2 + b2 + c2 + d2) * inv, (a3 + b3 + c3 + d3) * inv);
    *(float4*)&agg[(size_t)w * 128 + lane * 4] = o;
}

__global__ void gather3_final(const float* __restrict__ bl, float* __restrict__ out) {
    int w = (blockIdx.x * blockDim.x + threadIdx.x) >> 5;
    if (w >= NN) return;
    int lane = threadIdx.x & 31;
    int s = g_start[w], e = g_start[w + 1];
    float inv = 1.f / fmaxf((float)(e - s), 1.f);
    float sum = 0.f;
    for (int i = s + lane; i < e; i += 32) {
        int r;
        asm volatile("ld.global.cg.u32 %0, [%1];" : "=r"(r) : "l"(&g_csrc[i]));
        float v;
        asm volatile("ld.global.cg.f32 %0, [%1];" : "=f"(v) : "l"(&g_s1[r]));
        sum += v;
    }
#pragma unroll
    for (int o = 16; o > 0; o >>= 1) sum += __shfl_down_sync(0xffffffffu, sum, o);
    if (lane == 0) out[w] = sum * inv + bl[0] + g_s2[w];
}

// ---------------- epilogue conv1: v = gelu(z + agg) -> fp16 ----------------
__global__ void ep_h(const float* __restrict__ z, const float* __restrict__ agg,
                     __half* __restrict__ o) {
    int i = blockIdx.x * blockDim.x + threadIdx.x;
    if (i >= NN * 32) return;
    float4 zv = *(const float4*)&z[(size_t)i * 4];
    float4 av = *(const float4*)&agg[(size_t)i * 4];
    __half2 o0 = __floats2half2_rn(gelu_f(zv.x + av.x), gelu_f(zv.y + av.y));
    __half2 o1 = __floats2half2_rn(gelu_f(zv.z + av.z), gelu_f(zv.w + av.w));
    *(__half2*)&o[(size_t)i * 4] = o0;
    *(__half2*)&o[(size_t)i * 4 + 2] = o1;
}

// ---------------- epilogue conv2 fused with conv3 dots ----------------
__global__ void ep2_conv3(const float* __restrict__ z, const float* __restrict__ agg,
                          const float* __restrict__ Wl, const float* __restrict__ Wr) {
    int w = (blockIdx.x * blockDim.x + threadIdx.x) >> 5;
    if (w >= NN) return;
    int lane = threadIdx.x & 31;
    size_t o = (size_t)w * 128 + lane * 4;
    float4 zv = *(const float4*)&z[o];
    float4 av = *(const float4*)&agg[o];
    float h0 = gelu_f(zv.x + av.x), h1 = gelu_f(zv.y + av.y);
    float h2 = gelu_f(zv.z + av.z), h3 = gelu_f(zv.w + av.w);
    float4 wl = *(const float4*)&Wl[lane * 4];
    float4 wr = *(const float4*)&Wr[lane * 4];
    float s1 = h0 * wl.x + h1 * wl.y + h2 * wl.z + h3 * wl.w;
    float s2 = h0 * wr.x + h1 * wr.y + h2 * wr.z + h3 * wr.w;
#pragma unroll
    for (int off = 16; off > 0; off >>= 1) {
        s1 += __shfl_down_sync(0xffffffffu, s1, off);
        s2 += __shfl_down_sync(0xffffffffu, s2, off);
    }
    if (lane == 0) { g_s1[w] = s1; g_s2[w] = s2; }
}

// =====================================================================
// single-fp16 tensor GEMM (row-range via mbase)
// =====================================================================
#define SMEM_DYN 32768

template<int K, int EPI, int OUTMODE, bool SPLIT>
__global__ void __launch_bounds__(256, 2)
tgemm_h(const __half* __restrict__ A, int lda,
        const __half* __restrict__ B,
        const float* __restrict__ bias,
        void* __restrict__ C0, int ldc,
        const __half* __restrict__ A2, const __half* __restrict__ B2,
        int mbase)
{
    extern __shared__ __align__(16) char sm[];

    const int tid  = threadIdx.x;
    const int m0   = mbase + blockIdx.x * 128;
    const int wid  = tid >> 5;
    const int lane = tid & 31;
    const int g    = lane >> 2;
    const int tig  = lane & 3;
    const int warpM = (wid >> 2) * 64;
    const int warpN = (wid & 3) * 32;

    constexpr int NC = K / 32;
    constexpr int BK = SPLIT ? 128 : K;
    const uint32_t smB = (uint32_t)__cvta_generic_to_shared(sm);

    const int laneT8 = lane & 7;
    const int aRow   = laneT8 + ((lane >> 3) & 1) * 8;
    const int aKh    = lane >> 4;
    const int bNsel  = lane >> 4;
    const int bKh    = (lane >> 3) & 1;

    float4 acc[4][4];
#pragma unroll
    for (int i = 0; i < 4; i++)
#pragma unroll
        for (int j = 0; j < 4; j++) acc[i][j] = make_float4(0.f, 0.f, 0.f, 0.f);

    auto copy_tile = [&](int buf, int k0) {
        uint32_t st = smB + (uint32_t)buf * 16384;
#pragma unroll
        for (int i = 0; i < 2; i++) {
            int flat = tid + i * 256;
            int r = flat >> 2, seg = flat & 3;
            int row = m0 + r; if (row >= NN) row = NN - 1;
            const __half* src;
            if (SPLIT && k0 >= 128) {
                src = A2 + (size_t)row * 64 + (k0 - 128) + seg * 8;
            } else {
                src = A + (size_t)row * lda + k0 + seg * 8;
            }
            uint32_t dst = st + (uint32_t)r * 64
                         + (uint32_t)((seg ^ ((r >> 1) & 3)) << 4);
            cpasync16(dst, src);
        }
#pragma unroll
        for (int i = 0; i < 2; i++) {
            int flat = tid + i * 256;
            int n = flat >> 2, seg = flat & 3;
            const __half* src;
            if (SPLIT && k0 >= 128) {
                src = B2 + (size_t)n * 64 + (k0 - 128) + seg * 8;
            } else {
                src = B + (size_t)n * BK + k0 + seg * 8;
            }
            uint32_t dst = st + 8192u + (uint32_t)n * 64
                         + (uint32_t)((seg ^ ((n >> 1) & 3)) << 4);
            cpasync16(dst, src);
        }
        cp_commit();
    };

    copy_tile(0, 0);

    for (int ks = 0; ks < NC; ks++) {
        if (ks + 1 < NC) {
            copy_tile((ks + 1) & 1, (ks + 1) * 32);
            cp_wait<1>();
        } else {
            cp_wait<0>();
        }
        __syncthreads();

        const uint32_t stage = smB + (uint32_t)(ks & 1) * 16384;
        const uint32_t Abase = stage;
        const uint32_t Bbase = stage + 8192u;

#pragma unroll
        for (int kc = 0; kc < 2; kc++) {
            uint32_t bf[4][2];
#pragma unroll
            for (int p = 0; p < 2; p++) {
                int n = warpN + (p * 2 + bNsel) * 8 + laneT8;
                int seg = kc * 2 + bKh;
                uint32_t addr = Bbase + (uint32_t)n * 64
                              + (uint32_t)((seg ^ ((n >> 1) & 3)) << 4);
                ldmx4(bf[p * 2][0], bf[p * 2][1], bf[p * 2 + 1][0], bf[p * 2 + 1][1], addr);
            }
#pragma unroll
            for (int mt = 0; mt < 4; mt++) {
                int r = warpM + mt * 16 + aRow;
                int seg = kc * 2 + aKh;
                uint32_t addr = Abase + (uint32_t)r * 64
                              + (uint32_t)((seg ^ ((r >> 1) & 3)) << 4);
                uint32_t af[4];
                ldmx4(af[0], af[1], af[2], af[3], addr);
#pragma unroll
                for (int nt = 0; nt < 4; nt++)
                    mma_f16(acc[mt][nt], af, bf[nt]);
            }
        }
        __syncthreads();
    }

#pragma unroll
    for (int mt = 0; mt < 4; mt++) {
        int r0 = m0 + warpM + mt * 16 + g;
#pragma unroll
        for (int rr = 0; rr < 2; rr++) {
            int r = r0 + rr * 8;
            if (r >= NN) continue;
#pragma unroll
            for (int nt = 0; nt < 4; nt++) {
                int col = warpN + nt * 8 + tig * 2;
                float v0 = (rr == 0) ? acc[mt][nt].x : acc[mt][nt].z;
                float v1 = (rr == 0) ? acc[mt][nt].y : acc[mt][nt].w;
                if (bias) { v0 += bias[col]; v1 += bias[col + 1]; }
                if (EPI == 0) { v0 = gelu_f(v0); v1 = gelu_f(v1); }
                if (OUTMODE == 0) {
                    *(float2*)((float*)C0 + (size_t)r * ldc + col) = make_float2(v0, v1);
                } else {
                    *(__half2*)((__half*)C0 + (size_t)r * ldc + col) = __floats2half2_rn(v0, v1);
                }
            }
        }
    }
}

// ---------------- host ----------------
extern "C" void kernel_launch(void* const* d_in, const int* in_sizes, int n_in,
                              void* d_out, int out_size) {
    (void)n_in; (void)out_size;
    const int*   x_cat  = (const int*)  d_in[0];
    const float* x_cont = (const float*)d_in[1];
    const int*   ei     = (const int*)  d_in[2];
    const float* emb    = (const float*)d_in[3];
    const float* W1     = (const float*)d_in[4];
    const float* b1     = (const float*)d_in[5];
    const float* W2     = (const float*)d_in[6];
    const float* b2     = (const float*)d_in[7];
    const float* W3     = (const float*)d_in[8];
    const float* b3     = (const float*)d_in[9];
    const float* c1_Wl  = (const float*)d_in[10];
    const float* c1_bl  = (const float*)d_in[11];
    const float* c1_Wr  = (const float*)d_in[12];
    const float* c2_Wl  = (const float*)d_in[13];
    const float* c2_bl  = (const float*)d_in[14];
    const float* c2_Wr  = (const float*)d_in[15];
    const float* c3_Wl  = (const float*)d_in[16];
    const float* c3_bl  = (const float*)d_in[17];
    const float* c3_Wr  = (const float*)d_in[18];
    float* out = (float*)d_out;

    const int E = in_sizes[2] / 2;

    __half *p_c, *p1, *p2, *p_y, *wt;
    float *p_z, *p_agg, *p_bfl, *p_bfr;
    cudaGetSymbolAddress((void**)&p_c, g_c);
    cudaGetSymbolAddress((void**)&p1, g_p1);
    cudaGetSymbolAddress((void**)&p2, g_p2);
    cudaGetSymbolAddress((void**)&p_y, g_y);
    cudaGetSymbolAddress((void**)&p_z, g_z);
    cudaGetSymbolAddress((void**)&p_agg, g_agg);
    cudaGetSymbolAddress((void**)&wt, g_wt);
    cudaGetSymbolAddress((void**)&p_bfl, g_bfl);
    cudaGetSymbolAddress((void**)&p_bfr, g_bfr);

    const int O_W2  = 0;
    const int O_FL  = 16384;
    const int O_FR  = 32768;
    const int O_CL  = 49152;
    const int O_CR  = 57344;
    const int O_C2L = 65536;
    const int O_C2R = 81920;

    static cudaStream_t s2 = nullptr, s3 = nullptr;
    static cudaEvent_t ev0, evE1, evE2, evP2, evY1, evG1, evY2, evG2;
    static bool init_done = false;
    if (!init_done) {
        cudaStreamCreateWithFlags(&s2, cudaStreamNonBlocking);
        cudaStreamCreateWithFlags(&s3, cudaStreamNonBlocking);
        cudaEventCreateWithFlags(&ev0, cudaEventDisableTiming);
        cudaEventCreateWithFlags(&evE1, cudaEventDisableTiming);
        cudaEventCreateWithFlags(&evE2, cudaEventDisableTiming);
        cudaEventCreateWithFlags(&evP2, cudaEventDisableTiming);
        cudaEventCreateWithFlags(&evY1, cudaEventDisableTiming);
        cudaEventCreateWithFlags(&evG1, cudaEventDisableTiming);
        cudaEventCreateWithFlags(&evY2, cudaEventDisableTiming);
        cudaEventCreateWithFlags(&evG2, cudaEventDisableTiming);
        cudaFuncSetAttribute(tgemm_h<128, 0, 2, false>, cudaFuncAttributeMaxDynamicSharedMemorySize, SMEM_DYN);
        cudaFuncSetAttribute(tgemm_h<192, 1, 2, true>,  cudaFuncAttributeMaxDynamicSharedMemorySize, SMEM_DYN);
        cudaFuncSetAttribute(tgemm_h<192, 1, 0, true>,  cudaFuncAttributeMaxDynamicSharedMemorySize, SMEM_DYN);
        cudaFuncSetAttribute(tgemm_h<128, 1, 2, false>, cudaFuncAttributeMaxDynamicSharedMemorySize, SMEM_DYN);
        cudaFuncSetAttribute(tgemm_h<128, 1, 0, false>, cudaFuncAttributeMaxDynamicSharedMemorySize, SMEM_DYN);
        init_done = true;
    }

    const int GB  = (NN + 127) / 128;
    const int GB1 = C1ROWS / 128;                      // 391
    const int GB2 = (NN - C1ROWS + 127) / 128;         // 391
    cudaStream_t ms = 0;

    cudaEventRecord(ev0, ms);
    cudaStreamWaitEvent(s2, ev0, 0);
    cudaStreamWaitEvent(s3, ev0, 0);

    // s2: CSR build
    zero_cnt<<<(NN + 255) / 256, 256, 0, s2>>>();
    count_k<<<(E + 255) / 256, 256, 0, s2>>>(ei, E);
    scan_block<<<NB_SCAN, 1024, 0, s2>>>();
    scan_top<<<1, 32, 0, s2>>>();
    scan_add<<<(NN + 255) / 256, 256, 0, s2>>>();
    fill_k<<<(E + 255) / 256, 256, 0, s2>>>(ei, E);

    // s3: weight prep + folding, then pipelined W2 chunks
    prep_weight<<<(128 * 128 + 255) / 256, 256, 0, s3>>>(W2, 128, wt + O_W2);
    fold_w3<<<64, 256, 0, s3>>>(W3, c1_Wl, b3, nullptr, wt + O_FL, p_bfl);
    fold_w3<<<64, 256, 0, s3>>>(W3, c1_Wr, b3, c1_bl,   wt + O_FR, p_bfr);
    prep_weight<<<(128 * 64 + 255) / 256, 256, 0, s3>>>(c1_Wl + 128 * 128, 64, wt + O_CL);
    prep_weight<<<(128 * 64 + 255) / 256, 256, 0, s3>>>(c1_Wr + 128 * 128, 64, wt + O_CR);
    prep_weight<<<(128 * 128 + 255) / 256, 256, 0, s3>>>(c2_Wl, 128, wt + O_C2L);
    prep_weight<<<(128 * 128 + 255) / 256, 256, 0, s3>>>(c2_Wr, 128, wt + O_C2R);

    // ms: table prep + emb_mlp1 chunk 1
    prep_T<<<NCAT * 2, 256, 0, ms>>>(emb, W1);
    copy_cont_h<<<(NN * 32 + 255) / 256, 256, 0, ms>>>(x_cont);
    emb_mlp1<<<(C1ROWS * 32 + 255) / 256, 256, 0, ms>>>(x_cat, b1, p1, 0, C1ROWS);
    cudaEventRecord(evE1, ms);
    // W2 chunk 1 on s3 overlaps emb chunk 2 on ms
    cudaStreamWaitEvent(s3, evE1, 0);
    tgemm_h<128, 0, 2, false><<<GB1, 256, SMEM_DYN, s3>>>(p1, 128, wt + O_W2, b2, p2, 128,
                                                          nullptr, nullptr, 0);
    emb_mlp1<<<((NN - C1ROWS) * 32 + 255) / 256, 256, 0, ms>>>(x_cat, b1, p1, C1ROWS, NN - C1ROWS);
    cudaEventRecord(evE2, ms);
    cudaStreamWaitEvent(s3, evE2, 0);
    tgemm_h<128, 0, 2, false><<<GB2, 256, SMEM_DYN, s3>>>(p1, 128, wt + O_W2, b2, p2, 128,
                                                          nullptr, nullptr, C1ROWS);
    cudaEventRecord(evP2, s3);
    cudaStreamWaitEvent(ms, evP2, 0);

    // ---- conv1: y = h2@Wfl + xc@Wlc + bfl (fp16); gather on s2; z = h2@Wfr + xc@Wrc + bfr
    tgemm_h<192, 1, 2, true><<<GB, 256, SMEM_DYN, ms>>>(p2, 128, wt + O_FL, p_bfl, p_y, 128,
                                                        p_c, wt + O_CL, 0);
    cudaEventRecord(evY1, ms);
    cudaStreamWaitEvent(s2, evY1, 0);
    gather_vec<<<(NN * 32 + 255) / 256, 256, 0, s2>>>(p_y, p_agg);
    cudaEventRecord(evG1, s2);
    tgemm_h<192, 1, 0, true><<<GB, 256, SMEM_DYN, ms>>>(p2, 128, wt + O_FR, p_bfr, p_z, 128,
                                                        p_c, wt + O_CR, 0);
    cudaStreamWaitEvent(ms, evG1, 0);
    ep_h<<<(NN * 32 + 255) / 256, 256, 0, ms>>>(p_z, p_agg, p1);

    // ---- conv2
    tgemm_h<128, 1, 2, false><<<GB, 256, SMEM_DYN, ms>>>(p1, 128, wt + O_C2L, nullptr, p_y, 128,
                                                         nullptr, nullptr, 0);
    cudaEventRecord(evY2, ms);
    cudaStreamWaitEvent(s2, evY2, 0);
    gather_vec<<<(NN * 32 + 255) / 256, 256, 0, s2>>>(p_y, p_agg);
    cudaEventRecord(evG2, s2);
    tgemm_h<128, 1, 0, false><<<GB, 256, SMEM_DYN, ms>>>(p1, 128, wt + O_C2R, c2_bl, p_z, 128,
                                                         nullptr, nullptr, 0);
    cudaStreamWaitEvent(ms, evG2, 0);

    // ---- conv2 epilogue fused with conv3 dots, then final gather
    ep2_conv3<<<(NN * 32 + 255) / 256, 256, 0, ms>>>(p_z, p_agg, c3_Wl, c3_Wr);
    gather3_final<<<(NN * 32 + 255) / 256, 256, 0, ms>>>(c3_bl, out);
}

// round 14
// speedup vs baseline: 1.0178x; 1.0178x over previous
#include <cuda_runtime.h>
#include <cuda_bf16.h>
#include <cuda_fp16.h>
#include <cstdint>
#include <math.h>

#define NN   100000
#define NE   1600000
#define NCAT 20
#define EMBD 32
#define CARD 100
#define NB_SCAN 98   // ceil(NN/1024)

// ---------------- scratch (device globals) ----------------
__device__ __half g_c[(size_t)NN * 64];           // x_cont fp16
__device__ __half g_p1[(size_t)NN * 128];         // layer buffers (fp16)
__device__ __half g_p2[(size_t)NN * 128];
__device__ __half g_y[(size_t)NN * 128];          // fp16 pre-aggregation features
__device__ float g_z[(size_t)NN * 128];
__device__ float g_agg[(size_t)NN * 128];
__device__ float g_s1[NN], g_s2[NN];
__device__ __half g_wt[768 * 128];                // [n][k] transposed fp16 weights
__device__ float g_bfl[128], g_bfr[128];          // folded conv1 biases
__device__ __half g_Th[NCAT * CARD * 128];        // fused emb@W1 tables (fp16)
// CSR
__device__ int g_cnt[NN];
__device__ int g_start[NN + 1];
__device__ int g_cursor[NN];
__device__ int g_csrc[NE];
__device__ int g_bsum[NB_SCAN];

__device__ __forceinline__ float gelu_f(float v) {
    return 0.5f * v * (1.0f + erff(v * 0.70710678118654752f));
}
__device__ __forceinline__ void mma_f16(float4& c, const uint32_t* a, const uint32_t* b) {
    asm volatile("mma.sync.aligned.m16n8k16.row.col.f32.f16.f16.f32 "
                 "{%0,%1,%2,%3}, {%4,%5,%6,%7}, {%8,%9}, {%0,%1,%2,%3};"
                 : "+f"(c.x), "+f"(c.y), "+f"(c.z), "+f"(c.w)
                 : "r"(a[0]), "r"(a[1]), "r"(a[2]), "r"(a[3]), "r"(b[0]), "r"(b[1]));
}
__device__ __forceinline__ void ldmx4(uint32_t& r0, uint32_t& r1, uint32_t& r2, uint32_t& r3,
                                      uint32_t addr) {
    asm volatile("ldmatrix.sync.aligned.m8n8.x4.shared.b16 {%0,%1,%2,%3}, [%4];"
                 : "=r"(r0), "=r"(r1), "=r"(r2), "=r"(r3) : "r"(addr));
}
__device__ __forceinline__ void cpasync16(uint32_t dst, const void* src) {
    asm volatile("cp.async.cg.shared.global [%0], [%1], 16;" :: "r"(dst), "l"(src));
}
__device__ __forceinline__ void cp_commit() { asm volatile("cp.async.commit_group;"); }
template<int N> __device__ __forceinline__ void cp_wait() {
    asm volatile("cp.async.wait_group %0;" :: "n"(N));
}

// ---------------- prep kernels ----------------
__global__ void prep_weight(const float* __restrict__ W, int K, __half* __restrict__ o) {
    int i = blockIdx.x * blockDim.x + threadIdx.x;
    if (i < 128 * K) {
        int k = i >> 7, n = i & 127;
        o[(size_t)n * K + k] = __float2half(W[i]);
    }
}
__global__ void __launch_bounds__(256)
fold_w3(const float* __restrict__ W3, const float* __restrict__ cW,
        const float* __restrict__ b3, const float* __restrict__ extra_bias,
        __half* __restrict__ o, float* __restrict__ obias) {
    int idx = blockIdx.x * 256 + threadIdx.x;
    int k = idx >> 7, n = idx & 127;
    float acc = 0.f;
    for (int d = 0; d < 128; d++)
        acc += W3[k * 128 + d] * cW[d * 128 + n];
    o[(size_t)n * 128 + k] = __float2half(acc);
    if (k == 0) {
        float bacc = extra_bias ? extra_bias[n] : 0.f;
        for (int d = 0; d < 128; d++) bacc += b3[d] * cW[d * 128 + n];
        obias[n] = bacc;
    }
}
__global__ void copy_cont_h(const float* __restrict__ xc) {
    int i = blockIdx.x * blockDim.x + threadIdx.x;
    if (i < NN * 32) {
        float2 v = *(const float2*)&xc[(size_t)i * 2];
        *(__half2*)&g_c[(size_t)i * 2] = __floats2half2_rn(v.x, v.y);
    }
}

// ---------------- emb@W1 table precompute (fp16 output) ----------------
__global__ void __launch_bounds__(256)
prep_T(const float* __restrict__ emb, const float* __restrict__ W1) {
    __shared__ float se[50 * 32];
    __shared__ float sw[32 * 128];
    int c = blockIdx.x >> 1;
    int rh = blockIdx.x & 1;
    int tid = threadIdx.x;
    for (int i = tid; i < 50 * 32; i += 256)
        se[i] = emb[(size_t)c * CARD * EMBD + rh * 50 * 32 + i];
    for (int i = tid; i < 32 * 128; i += 256)
        sw[i] = W1[(size_t)(c * 32) * 128 + i];
    __syncthreads();
    for (int i = 0; i < 25; i++) {
        int idx = tid + i * 256;
        int r = idx >> 7, n = idx & 127;
        float acc = 0.f;
#pragma unroll
        for (int d = 0; d < 32; d++)
            acc += se[r * 32 + d] * sw[d * 128 + n];
        g_Th[((size_t)c * CARD + rh * 50 + r) * 128 + n] = __float2half(acc);
    }
}

// ---------------- MLP layer 1 via fp16 table lookup-sum ----------------
__global__ void __launch_bounds__(256)
emb_mlp1(const int* __restrict__ xcat, const float* __restrict__ b1,
         __half* __restrict__ o) {
    int w = (blockIdx.x * blockDim.x + threadIdx.x) >> 5;
    if (w >= NN) return;
    int lane = threadIdx.x & 31;
    const int* xc = xcat + (size_t)w * NCAT;
    float4 acc = *(const float4*)&b1[lane * 4];
#pragma unroll
    for (int c = 0; c < NCAT; c++) {
        int cat = __ldg(&xc[c]);
        uint2 u = *(const uint2*)&g_Th[((size_t)c * CARD + cat) * 128 + lane * 4];
        float2 f0 = __half22float2(*(__half2*)&u.x);
        float2 f1 = __half22float2(*(__half2*)&u.y);
        acc.x += f0.x; acc.y += f0.y; acc.z += f1.x; acc.w += f1.y;
    }
    __half2 o0 = __floats2half2_rn(gelu_f(acc.x), gelu_f(acc.y));
    __half2 o1 = __floats2half2_rn(gelu_f(acc.z), gelu_f(acc.w));
    size_t off = (size_t)w * 128 + lane * 4;
    *(__half2*)&o[off] = o0;
    *(__half2*)&o[off + 2] = o1;
}

// ---------------- CSR build ----------------
__global__ void zero_cnt() {
    int i = blockIdx.x * blockDim.x + threadIdx.x;
    if (i < NN) g_cnt[i] = 0;
}
__global__ void count_k(const int* __restrict__ ei, int E) {
    int e = blockIdx.x * blockDim.x + threadIdx.x;
    if (e < E) atomicAdd(&g_cnt[ei[E + e]], 1);
}
__global__ void scan_block() {
    __shared__ int sh[1024];
    int tid = threadIdx.x;
    int i = blockIdx.x * 1024 + tid;
    int v = (i < NN) ? g_cnt[i] : 0;
    sh[tid] = v;
    __syncthreads();
#pragma unroll
    for (int off = 1; off < 1024; off <<= 1) {
        int t = (tid >= off) ? sh[tid - off] : 0;
        __syncthreads();
        sh[tid] += t;
        __syncthreads();
    }
    if (i < NN) g_start[i] = sh[tid] - v;
    if (tid == 1023) g_bsum[blockIdx.x] = sh[1023];
}
__global__ void scan_top() {
    if (threadIdx.x == 0) {
        int acc = 0;
        for (int j = 0; j < NB_SCAN; j++) { int t = g_bsum[j]; g_bsum[j] = acc; acc += t; }
        g_start[NN] = acc;
    }
}
__global__ void scan_add() {
    int i = blockIdx.x * blockDim.x + threadIdx.x;
    if (i < NN) {
        int s = g_start[i] + g_bsum[i >> 10];
        g_start[i] = s;
        g_cursor[i] = s;
    }
}
__global__ void fill_k(const int* __restrict__ ei, int E) {
    int e = blockIdx.x * blockDim.x + threadIdx.x;
    if (e < E) {
        int dst = ei[E + e];
        int pos = atomicAdd(&g_cursor[dst], 1);
        g_csrc[pos] = ei[e];
    }
}

// ---------------- gather kernels ----------------
// warp per node, 4-edge unroll, L1-cached loads (y rows reused ~deg times)
__global__ void gather_vec(const __half* __restrict__ y, float* __restrict__ agg) {
    int w = (blockIdx.x * blockDim.x + threadIdx.x) >> 5;
    if (w >= NN) return;
    int lane = threadIdx.x & 31;
    int s = g_start[w], e = g_start[w + 1];
    float inv = 1.f / fmaxf((float)(e - s), 1.f);
    float a0 = 0.f, a1 = 0.f, a2 = 0.f, a3 = 0.f;
    float b0 = 0.f, b1 = 0.f, b2 = 0.f, b3 = 0.f;
    float c0 = 0.f, c1 = 0.f, c2 = 0.f, c3 = 0.f;
    float d0 = 0.f, d1 = 0.f, d2 = 0.f, d3 = 0.f;
    int i = s;
    for (; i + 3 < e; i += 4) {
        int r0 = __ldg(&g_csrc[i]),     r1 = __ldg(&g_csrc[i + 1]);
        int r2 = __ldg(&g_csrc[i + 2]), r3 = __ldg(&g_csrc[i + 3]);
        uint2 u0 = *(const uint2*)&y[(size_t)r0 * 128 + lane * 4];
        uint2 u1 = *(const uint2*)&y[(size_t)r1 * 128 + lane * 4];
        uint2 u2 = *(const uint2*)&y[(size_t)r2 * 128 + lane * 4];
        uint2 u3 = *(const uint2*)&y[(size_t)r3 * 128 + lane * 4];
        float2 p0 = __half22float2(*(__half2*)&u0.x);
        float2 p1 = __half22float2(*(__half2*)&u0.y);
        float2 q0 = __half22float2(*(__half2*)&u1.x);
        float2 q1 = __half22float2(*(__half2*)&u1.y);
        float2 t0 = __half22float2(*(__half2*)&u2.x);
        float2 t1 = __half22float2(*(__half2*)&u2.y);
        float2 v0 = __half22float2(*(__half2*)&u3.x);
        float2 v1 = __half22float2(*(__half2*)&u3.y);
        a0 += p0.x; a1 += p0.y; a2 += p1.x; a3 += p1.y;
        b0 += q0.x; b1 += q0.y; b2 += q1.x; b3 += q1.y;
        c0 += t0.x; c1 += t0.y; c2 += t1.x; c3 += t1.y;
        d0 += v0.x; d1 += v0.y; d2 += v1.x; d3 += v1.y;
    }
    for (; i < e; i++) {
        int r0 = __ldg(&g_csrc[i]);
        uint2 u0 = *(const uint2*)&y[(size_t)r0 * 128 + lane * 4];
        float2 p0 = __half22float2(*(__half2*)&u0.x);
        float2 p1 = __half22float2(*(__half2*)&u0.y);
        a0 += p0.x; a1 += p0.y; a2 += p1.x; a3 += p1.y;
    }
    float4 o = make_float4((a0 + b0 + c0 + d0) * inv, (a1 + b1 + c1 + d1) * inv,
                           (a2 + b2 + c2 + d2) * inv, (a3 + b3 + c3 + d3) * inv);
    *(float4*)&agg[(size_t)w * 128 + lane * 4] = o;
}

__global__ void gather3_final(const float* __restrict__ bl, float* __restrict__ out) {
    int w = (blockIdx.x * blockDim.x + threadIdx.x) >> 5;
    if (w >= NN) return;
    int lane = threadIdx.x & 31;
    int s = g_start[w], e = g_start[w + 1];
    float inv = 1.f / fmaxf((float)(e - s), 1.f);
    float sum = 0.f;
    for (int i = s + lane; i < e; i += 32) sum += g_s1[g_csrc[i]];
#pragma unroll
    for (int o = 16; o > 0; o >>= 1) sum += __shfl_down_sync(0xffffffffu, sum, o);
    if (lane == 0) out[w] = sum * inv + bl[0] + g_s2[w];
}

// ---------------- epilogue conv1: v = gelu(z + agg) -> fp16 ----------------
__global__ void ep_h(const float* __restrict__ z, const float* __restrict__ agg,
                     __half* __restrict__ o) {
    int i = blockIdx.x * blockDim.x + threadIdx.x;
    if (i >= NN * 32) return;
    float4 zv = *(const float4*)&z[(size_t)i * 4];
    float4 av = *(const float4*)&agg[(size_t)i * 4];
    __half2 o0 = __floats2half2_rn(gelu_f(zv.x + av.x), gelu_f(zv.y + av.y));
    __half2 o1 = __floats2half2_rn(gelu_f(zv.z + av.z), gelu_f(zv.w + av.w));
    *(__half2*)&o[(size_t)i * 4] = o0;
    *(__half2*)&o[(size_t)i * 4 + 2] = o1;
}

// ---------------- epilogue conv2 fused with conv3 dots ----------------
__global__ void ep2_conv3(const float* __restrict__ z, const float* __restrict__ agg,
                          const float* __restrict__ Wl, const float* __restrict__ Wr) {
    int w = (blockIdx.x * blockDim.x + threadIdx.x) >> 5;
    if (w >= NN) return;
    int lane = threadIdx.x & 31;
    size_t o = (size_t)w * 128 + lane * 4;
    float4 zv = *(const float4*)&z[o];
    float4 av = *(const float4*)&agg[o];
    float h0 = gelu_f(zv.x + av.x), h1 = gelu_f(zv.y + av.y);
    float h2 = gelu_f(zv.z + av.z), h3 = gelu_f(zv.w + av.w);
    float4 wl = *(const float4*)&Wl[lane * 4];
    float4 wr = *(const float4*)&Wr[lane * 4];
    float s1 = h0 * wl.x + h1 * wl.y + h2 * wl.z + h3 * wl.w;
    float s2 = h0 * wr.x + h1 * wr.y + h2 * wr.z + h3 * wr.w;
#pragma unroll
    for (int off = 16; off > 0; off >>= 1) {
        s1 += __shfl_down_sync(0xffffffffu, s1, off);
        s2 += __shfl_down_sync(0xffffffffu, s2, off);
    }
    if (lane == 0) { g_s1[w] = s1; g_s2[w] = s2; }
}

// =====================================================================
// single-fp16 tensor GEMM with ldmatrix fragment loads
// =====================================================================
#define SMEM_DYN 32768

template<int K, int EPI, int OUTMODE, bool SPLIT>
__global__ void __launch_bounds__(256, 2)
tgemm_h(const __half* __restrict__ A, int lda,
        const __half* __restrict__ B,
        const float* __restrict__ bias,
        void* __restrict__ C0, int ldc,
        const __half* __restrict__ A2, const __half* __restrict__ B2)
{
    extern __shared__ __align__(16) char sm[];

    const int tid  = threadIdx.x;
    const int m0   = blockIdx.x * 128;
    const int wid  = tid >> 5;
    const int lane = tid & 31;
    const int g    = lane >> 2;
    const int tig  = lane & 3;
    const int warpM = (wid >> 2) * 64;
    const int warpN = (wid & 3) * 32;

    constexpr int NC = K / 32;
    constexpr int BK = SPLIT ? 128 : K;
    const uint32_t smB = (uint32_t)__cvta_generic_to_shared(sm);

    const int laneT8 = lane & 7;
    const int aRow   = laneT8 + ((lane >> 3) & 1) * 8;
    const int aKh    = lane >> 4;
    const int bNsel  = lane >> 4;
    const int bKh    = (lane >> 3) & 1;

    float4 acc[4][4];
#pragma unroll
    for (int i = 0; i < 4; i++)
#pragma unroll
        for (int j = 0; j < 4; j++) acc[i][j] = make_float4(0.f, 0.f, 0.f, 0.f);

    auto copy_tile = [&](int buf, int k0) {
        uint32_t st = smB + (uint32_t)buf * 16384;
#pragma unroll
        for (int i = 0; i < 2; i++) {
            int flat = tid + i * 256;
            int r = flat >> 2, seg = flat & 3;
            int row = m0 + r; if (row >= NN) row = NN - 1;
            const __half* src;
            if (SPLIT && k0 >= 128) {
                src = A2 + (size_t)row * 64 + (k0 - 128) + seg * 8;
            } else {
                src = A + (size_t)row * lda + k0 + seg * 8;
            }
            uint32_t dst = st + (uint32_t)r * 64
                         + (uint32_t)((seg ^ ((r >> 1) & 3)) << 4);
            cpasync16(dst, src);
        }
#pragma unroll
        for (int i = 0; i < 2; i++) {
            int flat = tid + i * 256;
            int n = flat >> 2, seg = flat & 3;
            const __half* src;
            if (SPLIT && k0 >= 128) {
                src = B2 + (size_t)n * 64 + (k0 - 128) + seg * 8;
            } else {
                src = B + (size_t)n * BK + k0 + seg * 8;
            }
            uint32_t dst = st + 8192u + (uint32_t)n * 64
                         + (uint32_t)((seg ^ ((n >> 1) & 3)) << 4);
            cpasync16(dst, src);
        }
        cp_commit();
    };

    copy_tile(0, 0);

    for (int ks = 0; ks < NC; ks++) {
        if (ks + 1 < NC) {
            copy_tile((ks + 1) & 1, (ks + 1) * 32);
            cp_wait<1>();
        } else {
            cp_wait<0>();
        }
        __syncthreads();

        const uint32_t stage = smB + (uint32_t)(ks & 1) * 16384;
        const uint32_t Abase = stage;
        const uint32_t Bbase = stage + 8192u;

#pragma unroll
        for (int kc = 0; kc < 2; kc++) {
            uint32_t bf[4][2];
#pragma unroll
            for (int p = 0; p < 2; p++) {
                int n = warpN + (p * 2 + bNsel) * 8 + laneT8;
                int seg = kc * 2 + bKh;
                uint32_t addr = Bbase + (uint32_t)n * 64
                              + (uint32_t)((seg ^ ((n >> 1) & 3)) << 4);
                ldmx4(bf[p * 2][0], bf[p * 2][1], bf[p * 2 + 1][0], bf[p * 2 + 1][1], addr);
            }
#pragma unroll
            for (int mt = 0; mt < 4; mt++) {
                int r = warpM + mt * 16 + aRow;
                int seg = kc * 2 + aKh;
                uint32_t addr = Abase + (uint32_t)r * 64
                              + (uint32_t)((seg ^ ((r >> 1) & 3)) << 4);
                uint32_t af[4];
                ldmx4(af[0], af[1], af[2], af[3], addr);
#pragma unroll
                for (int nt = 0; nt < 4; nt++)
                    mma_f16(acc[mt][nt], af, bf[nt]);
            }
        }
        __syncthreads();
    }

#pragma unroll
    for (int mt = 0; mt < 4; mt++) {
        int r0 = m0 + warpM + mt * 16 + g;
#pragma unroll
        for (int rr = 0; rr < 2; rr++) {
            int r = r0 + rr * 8;
            if (r >= NN) continue;
#pragma unroll
            for (int nt = 0; nt < 4; nt++) {
                int col = warpN + nt * 8 + tig * 2;
                float v0 = (rr == 0) ? acc[mt][nt].x : acc[mt][nt].z;
                float v1 = (rr == 0) ? acc[mt][nt].y : acc[mt][nt].w;
                if (bias) { v0 += bias[col]; v1 += bias[col + 1]; }
                if (EPI == 0) { v0 = gelu_f(v0); v1 = gelu_f(v1); }
                if (OUTMODE == 0) {
                    *(float2*)((float*)C0 + (size_t)r * ldc + col) = make_float2(v0, v1);
                } else {
                    *(__half2*)((__half*)C0 + (size_t)r * ldc + col) = __floats2half2_rn(v0, v1);
                }
            }
        }
    }
}

// ---------------- host ----------------
extern "C" void kernel_launch(void* const* d_in, const int* in_sizes, int n_in,
                              void* d_out, int out_size) {
    (void)n_in; (void)out_size;
    const int*   x_cat  = (const int*)  d_in[0];
    const float* x_cont = (const float*)d_in[1];
    const int*   ei     = (const int*)  d_in[2];
    const float* emb    = (const float*)d_in[3];
    const float* W1     = (const float*)d_in[4];
    const float* b1     = (const float*)d_in[5];
    const float* W2     = (const float*)d_in[6];
    const float* b2     = (const float*)d_in[7];
    const float* W3     = (const float*)d_in[8];
    const float* b3     = (const float*)d_in[9];
    const float* c1_Wl  = (const float*)d_in[10];
    const float* c1_bl  = (const float*)d_in[11];
    const float* c1_Wr  = (const float*)d_in[12];
    const float* c2_Wl  = (const float*)d_in[13];
    const float* c2_bl  = (const float*)d_in[14];
    const float* c2_Wr  = (const float*)d_in[15];
    const float* c3_Wl  = (const float*)d_in[16];
    const float* c3_bl  = (const float*)d_in[17];
    const float* c3_Wr  = (const float*)d_in[18];
    float* out = (float*)d_out;

    const int E = in_sizes[2] / 2;

    __half *p_c, *p1, *p2, *p_y, *wt;
    float *p_z, *p_agg, *p_bfl, *p_bfr;
    cudaGetSymbolAddress((void**)&p_c, g_c);
    cudaGetSymbolAddress((void**)&p1, g_p1);
    cudaGetSymbolAddress((void**)&p2, g_p2);
    cudaGetSymbolAddress((void**)&p_y, g_y);
    cudaGetSymbolAddress((void**)&p_z, g_z);
    cudaGetSymbolAddress((void**)&p_agg, g_agg);
    cudaGetSymbolAddress((void**)&wt, g_wt);
    cudaGetSymbolAddress((void**)&p_bfl, g_bfl);
    cudaGetSymbolAddress((void**)&p_bfr, g_bfr);

    const int O_W2  = 0;
    const int O_FL  = 16384;
    const int O_FR  = 32768;
    const int O_CL  = 49152;
    const int O_CR  = 57344;
    const int O_C2L = 65536;
    const int O_C2R = 81920;

    static cudaStream_t s2 = nullptr, s3 = nullptr;
    static cudaEvent_t ev0, evW, evY1, evG1, evY2, evG2;
    static bool init_done = false;
    if (!init_done) {
        cudaStreamCreateWithFlags(&s2, cudaStreamNonBlocking);
        cudaStreamCreateWithFlags(&s3, cudaStreamNonBlocking);
        cudaEventCreateWithFlags(&ev0, cudaEventDisableTiming);
        cudaEventCreateWithFlags(&evW, cudaEventDisableTiming);
        cudaEventCreateWithFlags(&evY1, cudaEventDisableTiming);
        cudaEventCreateWithFlags(&evG1, cudaEventDisableTiming);
        cudaEventCreateWithFlags(&evY2, cudaEventDisableTiming);
        cudaEventCreateWithFlags(&evG2, cudaEventDisableTiming);
        cudaFuncSetAttribute(tgemm_h<128, 0, 2, false>, cudaFuncAttributeMaxDynamicSharedMemorySize, SMEM_DYN);
        cudaFuncSetAttribute(tgemm_h<192, 1, 2, true>,  cudaFuncAttributeMaxDynamicSharedMemorySize, SMEM_DYN);
        cudaFuncSetAttribute(tgemm_h<192, 1, 0, true>,  cudaFuncAttributeMaxDynamicSharedMemorySize, SMEM_DYN);
        cudaFuncSetAttribute(tgemm_h<128, 1, 2, false>, cudaFuncAttributeMaxDynamicSharedMemorySize, SMEM_DYN);
        cudaFuncSetAttribute(tgemm_h<128, 1, 0, false>, cudaFuncAttributeMaxDynamicSharedMemorySize, SMEM_DYN);
        init_done = true;
    }

    const int GB = (NN + 127) / 128;
    cudaStream_t ms = 0;

    cudaEventRecord(ev0, ms);
    cudaStreamWaitEvent(s2, ev0, 0);
    cudaStreamWaitEvent(s3, ev0, 0);

    // s2: CSR build
    zero_cnt<<<(NN + 255) / 256, 256, 0, s2>>>();
    count_k<<<(E + 255) / 256, 256, 0, s2>>>(ei, E);
    scan_block<<<NB_SCAN, 1024, 0, s2>>>();
    scan_top<<<1, 32, 0, s2>>>();
    scan_add<<<(NN + 255) / 256, 256, 0, s2>>>();
    fill_k<<<(E + 255) / 256, 256, 0, s2>>>(ei, E);

    // s3: weight prep + folding
    prep_weight<<<(128 * 128 + 255) / 256, 256, 0, s3>>>(W2, 128, wt + O_W2);
    fold_w3<<<64, 256, 0, s3>>>(W3, c1_Wl, b3, nullptr, wt + O_FL, p_bfl);
    fold_w3<<<64, 256, 0, s3>>>(W3, c1_Wr, b3, c1_bl,   wt + O_FR, p_bfr);
    prep_weight<<<(128 * 64 + 255) / 256, 256, 0, s3>>>(c1_Wl + 128 * 128, 64, wt + O_CL);
    prep_weight<<<(128 * 64 + 255) / 256, 256, 0, s3>>>(c1_Wr + 128 * 128, 64, wt + O_CR);
    prep_weight<<<(128 * 128 + 255) / 256, 256, 0, s3>>>(c2_Wl, 128, wt + O_C2L);
    prep_weight<<<(128 * 128 + 255) / 256, 256, 0, s3>>>(c2_Wr, 128, wt + O_C2R);
    cudaEventRecord(evW, s3);

    // ms: MLP layer 1 via fused fp16 tables
    prep_T<<<NCAT * 2, 256, 0, ms>>>(emb, W1);
    copy_cont_h<<<(NN * 32 + 255) / 256, 256, 0, ms>>>(x_cont);
    emb_mlp1<<<(NN * 32 + 255) / 256, 256, 0, ms>>>(x_cat, b1, p1);

    cudaStreamWaitEvent(ms, evW, 0);

    // MLP layer 2 (W3 folded into conv1)
    tgemm_h<128, 0, 2, false><<<GB, 256, SMEM_DYN, ms>>>(p1, 128, wt + O_W2, b2, p2, 128,
                                                         nullptr, nullptr);

    // ---- conv1: y = h2@Wfl + xc@Wlc + bfl (fp16); gather on s2; z = h2@Wfr + xc@Wrc + bfr
    tgemm_h<192, 1, 2, true><<<GB, 256, SMEM_DYN, ms>>>(p2, 128, wt + O_FL, p_bfl, p_y, 128,
                                                        p_c, wt + O_CL);
    cudaEventRecord(evY1, ms);
    cudaStreamWaitEvent(s2, evY1, 0);
    gather_vec<<<(NN * 32 + 255) / 256, 256, 0, s2>>>(p_y, p_agg);
    cudaEventRecord(evG1, s2);
    tgemm_h<192, 1, 0, true><<<GB, 256, SMEM_DYN, ms>>>(p2, 128, wt + O_FR, p_bfr, p_z, 128,
                                                        p_c, wt + O_CR);
    cudaStreamWaitEvent(ms, evG1, 0);
    ep_h<<<(NN * 32 + 255) / 256, 256, 0, ms>>>(p_z, p_agg, p1);

    // ---- conv2
    tgemm_h<128, 1, 2, false><<<GB, 256, SMEM_DYN, ms>>>(p1, 128, wt + O_C2L, nullptr, p_y, 128,
                                                         nullptr, nullptr);
    cudaEventRecord(evY2, ms);
    cudaStreamWaitEvent(s2, evY2, 0);
    gather_vec<<<(NN * 32 + 255) / 256, 256, 0, s2>>>(p_y, p_agg);
    cudaEventRecord(evG2, s2);
    tgemm_h<128, 1, 0, false><<<GB, 256, SMEM_DYN, ms>>>(p1, 128, wt + O_C2R, c2_bl, p_z, 128,
                                                         nullptr, nullptr);
    cudaStreamWaitEvent(ms, evG2, 0);

    // ---- conv2 epilogue fused with conv3 dots, then final gather
    ep2_conv3<<<(NN * 32 + 255) / 256, 256, 0, ms>>>(p_z, p_agg, c3_Wl, c3_Wr);
    gather3_final<<<(NN * 32 + 255) / 256, 256, 0, ms>>>(c3_bl, out);
}

// round 15
// speedup vs baseline: 1.0708x; 1.0521x over previous
#include <cuda_runtime.h>
#include <cuda_bf16.h>
#include <cuda_fp16.h>
#include <cstdint>
#include <math.h>

#define NN   100000
#define NE   1600000
#define NCAT 20
#define EMBD 32
#define CARD 100
#define NB_SCAN 98   // ceil(NN/1024)

// ---------------- scratch (device globals) ----------------
__device__ __half g_c[(size_t)NN * 64];           // x_cont fp16
__device__ __half g_p1[(size_t)NN * 128];         // layer buffers (fp16)
__device__ __half g_p2[(size_t)NN * 128];
__device__ __half g_y[(size_t)NN * 128];          // fp16 pre-aggregation features
__device__ float g_z[(size_t)NN * 128];
__device__ float g_agg[(size_t)NN * 128];
__device__ float g_s1[NN], g_s2[NN];
__device__ __half g_wt[768 * 128];                // [n][k] transposed fp16 weights
__device__ float g_bfl[128], g_bfr[128];          // folded conv1 biases
__device__ __half g_Th[NCAT * CARD * 128];        // fused emb@W1 tables (fp16)
// CSR
__device__ int g_cnt[NN];
__device__ int g_start[NN + 1];
__device__ int g_cursor[NN];
__device__ int g_csrc[NE];
__device__ int g_bsum[NB_SCAN];

__device__ __forceinline__ float gelu_f(float v) {
    return 0.5f * v * (1.0f + erff(v * 0.70710678118654752f));
}
__device__ __forceinline__ void mma_f16(float4& c, const uint32_t* a, const uint32_t* b) {
    asm volatile("mma.sync.aligned.m16n8k16.row.col.f32.f16.f16.f32 "
                 "{%0,%1,%2,%3}, {%4,%5,%6,%7}, {%8,%9}, {%0,%1,%2,%3};"
                 : "+f"(c.x), "+f"(c.y), "+f"(c.z), "+f"(c.w)
                 : "r"(a[0]), "r"(a[1]), "r"(a[2]), "r"(a[3]), "r"(b[0]), "r"(b[1]));
}
__device__ __forceinline__ void ldmx4(uint32_t& r0, uint32_t& r1, uint32_t& r2, uint32_t& r3,
                                      uint32_t addr) {
    asm volatile("ldmatrix.sync.aligned.m8n8.x4.shared.b16 {%0,%1,%2,%3}, [%4];"
                 : "=r"(r0), "=r"(r1), "=r"(r2), "=r"(r3) : "r"(addr));
}
__device__ __forceinline__ void cpasync16(uint32_t dst, const void* src) {
    asm volatile("cp.async.cg.shared.global [%0], [%1], 16;" :: "r"(dst), "l"(src));
}
__device__ __forceinline__ void cp_commit() { asm volatile("cp.async.commit_group;"); }
template<int N> __device__ __forceinline__ void cp_wait() {
    asm volatile("cp.async.wait_group %0;" :: "n"(N));
}

// ---------------- prep kernels ----------------
__global__ void prep_weight(const float* __restrict__ W, int K, __half* __restrict__ o) {
    int i = blockIdx.x * blockDim.x + threadIdx.x;
    if (i < 128 * K) {
        int k = i >> 7, n = i & 127;
        o[(size_t)n * K + k] = __float2half(W[i]);
    }
}
__global__ void __launch_bounds__(256)
fold_w3(const float* __restrict__ W3, const float* __restrict__ cW,
        const float* __restrict__ b3, const float* __restrict__ extra_bias,
        __half* __restrict__ o, float* __restrict__ obias) {
    int idx = blockIdx.x * 256 + threadIdx.x;
    int k = idx >> 7, n = idx & 127;
    float acc = 0.f;
    for (int d = 0; d < 128; d++)
        acc += W3[k * 128 + d] * cW[d * 128 + n];
    o[(size_t)n * 128 + k] = __float2half(acc);
    if (k == 0) {
        float bacc = extra_bias ? extra_bias[n] : 0.f;
        for (int d = 0; d < 128; d++) bacc += b3[d] * cW[d * 128 + n];
        obias[n] = bacc;
    }
}
__global__ void copy_cont_h(const float* __restrict__ xc) {
    int i = blockIdx.x * blockDim.x + threadIdx.x;
    if (i < NN * 32) {
        float2 v = *(const float2*)&xc[(size_t)i * 2];
        *(__half2*)&g_c[(size_t)i * 2] = __floats2half2_rn(v.x, v.y);
    }
}

// ---------------- emb@W1 table precompute (fp16 output) ----------------
__global__ void __launch_bounds__(256)
prep_T(const float* __restrict__ emb, const float* __restrict__ W1) {
    __shared__ float se[50 * 32];
    __shared__ float sw[32 * 128];
    int c = blockIdx.x >> 1;
    int rh = blockIdx.x & 1;
    int tid = threadIdx.x;
    for (int i = tid; i < 50 * 32; i += 256)
        se[i] = emb[(size_t)c * CARD * EMBD + rh * 50 * 32 + i];
    for (int i = tid; i < 32 * 128; i += 256)
        sw[i] = W1[(size_t)(c * 32) * 128 + i];
    __syncthreads();
    for (int i = 0; i < 25; i++) {
        int idx = tid + i * 256;
        int r = idx >> 7, n = idx & 127;
        float acc = 0.f;
#pragma unroll
        for (int d = 0; d < 32; d++)
            acc += se[r * 32 + d] * sw[d * 128 + n];
        g_Th[((size_t)c * CARD + rh * 50 + r) * 128 + n] = __float2half(acc);
    }
}

// ---------------- MLP layer 1 via fp16 table lookup-sum ----------------
__global__ void __launch_bounds__(256)
emb_mlp1(const int* __restrict__ xcat, const float* __restrict__ b1,
         __half* __restrict__ o) {
    int w = (blockIdx.x * blockDim.x + threadIdx.x) >> 5;
    if (w >= NN) return;
    int lane = threadIdx.x & 31;
    const int* xc = xcat + (size_t)w * NCAT;
    float4 acc = *(const float4*)&b1[lane * 4];
#pragma unroll
    for (int c = 0; c < NCAT; c++) {
        int cat = __ldg(&xc[c]);
        uint2 u = *(const uint2*)&g_Th[((size_t)c * CARD + cat) * 128 + lane * 4];
        float2 f0 = __half22float2(*(__half2*)&u.x);
        float2 f1 = __half22float2(*(__half2*)&u.y);
        acc.x += f0.x; acc.y += f0.y; acc.z += f1.x; acc.w += f1.y;
    }
    __half2 o0 = __floats2half2_rn(gelu_f(acc.x), gelu_f(acc.y));
    __half2 o1 = __floats2half2_rn(gelu_f(acc.z), gelu_f(acc.w));
    size_t off = (size_t)w * 128 + lane * 4;
    *(__half2*)&o[off] = o0;
    *(__half2*)&o[off + 2] = o1;
}

// ---------------- CSR build ----------------
__global__ void zero_cnt() {
    int i = blockIdx.x * blockDim.x + threadIdx.x;
    if (i < NN) g_cnt[i] = 0;
}
__global__ void count_k(const int* __restrict__ ei, int E) {
    int e = blockIdx.x * blockDim.x + threadIdx.x;
    if (e < E) atomicAdd(&g_cnt[ei[E + e]], 1);
}
__global__ void scan_block() {
    __shared__ int sh[1024];
    int tid = threadIdx.x;
    int i = blockIdx.x * 1024 + tid;
    int v = (i < NN) ? g_cnt[i] : 0;
    sh[tid] = v;
    __syncthreads();
#pragma unroll
    for (int off = 1; off < 1024; off <<= 1) {
        int t = (tid >= off) ? sh[tid - off] : 0;
        __syncthreads();
        sh[tid] += t;
        __syncthreads();
    }
    if (i < NN) g_start[i] = sh[tid] - v;
    if (tid == 1023) g_bsum[blockIdx.x] = sh[1023];
}
__global__ void scan_top() {
    if (threadIdx.x == 0) {
        int acc = 0;
        for (int j = 0; j < NB_SCAN; j++) { int t = g_bsum[j]; g_bsum[j] = acc; acc += t; }
        g_start[NN] = acc;
    }
}
__global__ void scan_add() {
    int i = blockIdx.x * blockDim.x + threadIdx.x;
    if (i < NN) {
        int s = g_start[i] + g_bsum[i >> 10];
        g_start[i] = s;
        g_cursor[i] = s;
    }
}
__global__ void fill_k(const int* __restrict__ ei, int E) {
    int e = blockIdx.x * blockDim.x + threadIdx.x;
    if (e < E) {
        int dst = ei[E + e];
        int pos = atomicAdd(&g_cursor[dst], 1);
        g_csrc[pos] = ei[e];
    }
}

// ---------------- gather kernels (R12 form — measured optimum) ----------------
__global__ void gather_vec(const __half* __restrict__ y, float* __restrict__ agg) {
    int w = (blockIdx.x * blockDim.x + threadIdx.x) >> 5;
    if (w >= NN) return;
    int lane = threadIdx.x & 31;
    int s = g_start[w], e = g_start[w + 1];
    float inv = 1.f / fmaxf((float)(e - s), 1.f);
    float a0 = 0.f, a1 = 0.f, a2 = 0.f, a3 = 0.f;
    float b0 = 0.f, b1 = 0.f, b2 = 0.f, b3 = 0.f;
    int i = s;
    for (; i + 1 < e; i += 2) {
        int r0 = g_csrc[i], r1 = g_csrc[i + 1];
        uint2 u0 = *(const uint2*)&y[(size_t)r0 * 128 + lane * 4];
        uint2 u1 = *(const uint2*)&y[(size_t)r1 * 128 + lane * 4];
        float2 p0 = __half22float2(*(__half2*)&u0.x);
        float2 p1 = __half22float2(*(__half2*)&u0.y);
        float2 q0 = __half22float2(*(__half2*)&u1.x);
        float2 q1 = __half22float2(*(__half2*)&u1.y);
        a0 += p0.x; a1 += p0.y; a2 += p1.x; a3 += p1.y;
        b0 += q0.x; b1 += q0.y; b2 += q1.x; b3 += q1.y;
    }
    if (i < e) {
        int r0 = g_csrc[i];
        uint2 u0 = *(const uint2*)&y[(size_t)r0 * 128 + lane * 4];
        float2 p0 = __half22float2(*(__half2*)&u0.x);
        float2 p1 = __half22float2(*(__half2*)&u0.y);
        a0 += p0.x; a1 += p0.y; a2 += p1.x; a3 += p1.y;
    }
    float4 o = make_float4((a0 + b0) * inv, (a1 + b1) * inv,
                           (a2 + b2) * inv, (a3 + b3) * inv);
    *(float4*)&agg[(size_t)w * 128 + lane * 4] = o;
}

__global__ void gather3_final(const float* __restrict__ bl, float* __restrict__ out) {
    int w = (blockIdx.x * blockDim.x + threadIdx.x) >> 5;
    if (w >= NN) return;
    int lane = threadIdx.x & 31;
    int s = g_start[w], e = g_start[w + 1];
    float inv = 1.f / fmaxf((float)(e - s), 1.f);
    float sum = 0.f;
    for (int i = s + lane; i < e; i += 32) sum += g_s1[g_csrc[i]];
#pragma unroll
    for (int o = 16; o > 0; o >>= 1) sum += __shfl_down_sync(0xffffffffu, sum, o);
    if (lane == 0) out[w] = sum * inv + bl[0] + g_s2[w];
}

// ---------------- epilogue conv1: v = gelu(z + agg) -> fp16 ----------------
__global__ void ep_h(const float* __restrict__ z, const float* __restrict__ agg,
                     __half* __restrict__ o) {
    int i = blockIdx.x * blockDim.x + threadIdx.x;
    if (i >= NN * 32) return;
    float4 zv = *(const float4*)&z[(size_t)i * 4];
    float4 av = *(const float4*)&agg[(size_t)i * 4];
    __half2 o0 = __floats2half2_rn(gelu_f(zv.x + av.x), gelu_f(zv.y + av.y));
    __half2 o1 = __floats2half2_rn(gelu_f(zv.z + av.z), gelu_f(zv.w + av.w));
    *(__half2*)&o[(size_t)i * 4] = o0;
    *(__half2*)&o[(size_t)i * 4 + 2] = o1;
}

// ---------------- epilogue conv2 fused with conv3 dots ----------------
__global__ void ep2_conv3(const float* __restrict__ z, const float* __restrict__ agg,
                          const float* __restrict__ Wl, const float* __restrict__ Wr) {
    int w = (blockIdx.x * blockDim.x + threadIdx.x) >> 5;
    if (w >= NN) return;
    int lane = threadIdx.x & 31;
    size_t o = (size_t)w * 128 + lane * 4;
    float4 zv = *(const float4*)&z[o];
    float4 av = *(const float4*)&agg[o];
    float h0 = gelu_f(zv.x + av.x), h1 = gelu_f(zv.y + av.y);
    float h2 = gelu_f(zv.z + av.z), h3 = gelu_f(zv.w + av.w);
    float4 wl = *(const float4*)&Wl[lane * 4];
    float4 wr = *(const float4*)&Wr[lane * 4];
    float s1 = h0 * wl.x + h1 * wl.y + h2 * wl.z + h3 * wl.w;
    float s2 = h0 * wr.x + h1 * wr.y + h2 * wr.z + h3 * wr.w;
#pragma unroll
    for (int off = 16; off > 0; off >>= 1) {
        s1 += __shfl_down_sync(0xffffffffu, s1, off);
        s2 += __shfl_down_sync(0xffffffffu, s2, off);
    }
    if (lane == 0) { g_s1[w] = s1; g_s2[w] = s2; }
}

// =====================================================================
// single-fp16 tensor GEMM with ldmatrix fragment loads
// =====================================================================
#define SMEM_DYN 32768

template<int K, int EPI, int OUTMODE, bool SPLIT>
__global__ void __launch_bounds__(256, 2)
tgemm_h(const __half* __restrict__ A, int lda,
        const __half* __restrict__ B,
        const float* __restrict__ bias,
        void* __restrict__ C0, int ldc,
        const __half* __restrict__ A2, const __half* __restrict__ B2)
{
    extern __shared__ __align__(16) char sm[];

    const int tid  = threadIdx.x;
    const int m0   = blockIdx.x * 128;
    const int wid  = tid >> 5;
    const int lane = tid & 31;
    const int g    = lane >> 2;
    const int tig  = lane & 3;
    const int warpM = (wid >> 2) * 64;
    const int warpN = (wid & 3) * 32;

    constexpr int NC = K / 32;
    constexpr int BK = SPLIT ? 128 : K;
    const uint32_t smB = (uint32_t)__cvta_generic_to_shared(sm);

    const int laneT8 = lane & 7;
    const int aRow   = laneT8 + ((lane >> 3) & 1) * 8;
    const int aKh    = lane >> 4;
    const int bNsel  = lane >> 4;
    const int bKh    = (lane >> 3) & 1;

    float4 acc[4][4];
#pragma unroll
    for (int i = 0; i < 4; i++)
#pragma unroll
        for (int j = 0; j < 4; j++) acc[i][j] = make_float4(0.f, 0.f, 0.f, 0.f);

    auto copy_tile = [&](int buf, int k0) {
        uint32_t st = smB + (uint32_t)buf * 16384;
#pragma unroll
        for (int i = 0; i < 2; i++) {
            int flat = tid + i * 256;
            int r = flat >> 2, seg = flat & 3;
            int row = m0 + r; if (row >= NN) row = NN - 1;
            const __half* src;
            if (SPLIT && k0 >= 128) {
                src = A2 + (size_t)row * 64 + (k0 - 128) + seg * 8;
            } else {
                src = A + (size_t)row * lda + k0 + seg * 8;
            }
            uint32_t dst = st + (uint32_t)r * 64
                         + (uint32_t)((seg ^ ((r >> 1) & 3)) << 4);
            cpasync16(dst, src);
        }
#pragma unroll
        for (int i = 0; i < 2; i++) {
            int flat = tid + i * 256;
            int n = flat >> 2, seg = flat & 3;
            const __half* src;
            if (SPLIT && k0 >= 128) {
                src = B2 + (size_t)n * 64 + (k0 - 128) + seg * 8;
            } else {
                src = B + (size_t)n * BK + k0 + seg * 8;
            }
            uint32_t dst = st + 8192u + (uint32_t)n * 64
                         + (uint32_t)((seg ^ ((n >> 1) & 3)) << 4);
            cpasync16(dst, src);
        }
        cp_commit();
    };

    copy_tile(0, 0);

    for (int ks = 0; ks < NC; ks++) {
        if (ks + 1 < NC) {
            copy_tile((ks + 1) & 1, (ks + 1) * 32);
            cp_wait<1>();
        } else {
            cp_wait<0>();
        }
        __syncthreads();

        const uint32_t stage = smB + (uint32_t)(ks & 1) * 16384;
        const uint32_t Abase = stage;
        const uint32_t Bbase = stage + 8192u;

#pragma unroll
        for (int kc = 0; kc < 2; kc++) {
            uint32_t bf[4][2];
#pragma unroll
            for (int p = 0; p < 2; p++) {
                int n = warpN + (p * 2 + bNsel) * 8 + laneT8;
                int seg = kc * 2 + bKh;
                uint32_t addr = Bbase + (uint32_t)n * 64
                              + (uint32_t)((seg ^ ((n >> 1) & 3)) << 4);
                ldmx4(bf[p * 2][0], bf[p * 2][1], bf[p * 2 + 1][0], bf[p * 2 + 1][1], addr);
            }
#pragma unroll
            for (int mt = 0; mt < 4; mt++) {
                int r = warpM + mt * 16 + aRow;
                int seg = kc * 2 + aKh;
                uint32_t addr = Abase + (uint32_t)r * 64
                              + (uint32_t)((seg ^ ((r >> 1) & 3)) << 4);
                uint32_t af[4];
                ldmx4(af[0], af[1], af[2], af[3], addr);
#pragma unroll
                for (int nt = 0; nt < 4; nt++)
                    mma_f16(acc[mt][nt], af, bf[nt]);
            }
        }
        __syncthreads();
    }

#pragma unroll
    for (int mt = 0; mt < 4; mt++) {
        int r0 = m0 + warpM + mt * 16 + g;
#pragma unroll
        for (int rr = 0; rr < 2; rr++) {
            int r = r0 + rr * 8;
            if (r >= NN) continue;
#pragma unroll
            for (int nt = 0; nt < 4; nt++) {
                int col = warpN + nt * 8 + tig * 2;
                float v0 = (rr == 0) ? acc[mt][nt].x : acc[mt][nt].z;
                float v1 = (rr == 0) ? acc[mt][nt].y : acc[mt][nt].w;
                if (bias) { v0 += bias[col]; v1 += bias[col + 1]; }
                if (EPI == 0) { v0 = gelu_f(v0); v1 = gelu_f(v1); }
                if (OUTMODE == 0) {
                    *(float2*)((float*)C0 + (size_t)r * ldc + col) = make_float2(v0, v1);
                } else {
                    *(__half2*)((__half*)C0 + (size_t)r * ldc + col) = __floats2half2_rn(v0, v1);
                }
            }
        }
    }
}

// ---------------- host ----------------
extern "C" void kernel_launch(void* const* d_in, const int* in_sizes, int n_in,
                              void* d_out, int out_size) {
    (void)n_in; (void)out_size;
    const int*   x_cat  = (const int*)  d_in[0];
    const float* x_cont = (const float*)d_in[1];
    const int*   ei     = (const int*)  d_in[2];
    const float* emb    = (const float*)d_in[3];
    const float* W1     = (const float*)d_in[4];
    const float* b1     = (const float*)d_in[5];
    const float* W2     = (const float*)d_in[6];
    const float* b2     = (const float*)d_in[7];
    const float* W3     = (const float*)d_in[8];
    const float* b3     = (const float*)d_in[9];
    const float* c1_Wl  = (const float*)d_in[10];
    const float* c1_bl  = (const float*)d_in[11];
    const float* c1_Wr  = (const float*)d_in[12];
    const float* c2_Wl  = (const float*)d_in[13];
    const float* c2_bl  = (const float*)d_in[14];
    const float* c2_Wr  = (const float*)d_in[15];
    const float* c3_Wl  = (const float*)d_in[16];
    const float* c3_bl  = (const float*)d_in[17];
    const float* c3_Wr  = (const float*)d_in[18];
    float* out = (float*)d_out;

    const int E = in_sizes[2] / 2;

    __half *p_c, *p1, *p2, *p_y, *wt;
    float *p_z, *p_agg, *p_bfl, *p_bfr;
    cudaGetSymbolAddress((void**)&p_c, g_c);
    cudaGetSymbolAddress((void**)&p1, g_p1);
    cudaGetSymbolAddress((void**)&p2, g_p2);
    cudaGetSymbolAddress((void**)&p_y, g_y);
    cudaGetSymbolAddress((void**)&p_z, g_z);
    cudaGetSymbolAddress((void**)&p_agg, g_agg);
    cudaGetSymbolAddress((void**)&wt, g_wt);
    cudaGetSymbolAddress((void**)&p_bfl, g_bfl);
    cudaGetSymbolAddress((void**)&p_bfr, g_bfr);

    const int O_W2  = 0;
    const int O_FL  = 16384;
    const int O_FR  = 32768;
    const int O_CL  = 49152;
    const int O_CR  = 57344;
    const int O_C2L = 65536;
    const int O_C2R = 81920;

    static cudaStream_t s2 = nullptr, s3 = nullptr;
    static cudaEvent_t ev0, evW, evY1, evG1, evY2, evG2;
    static bool init_done = false;
    if (!init_done) {
        cudaStreamCreateWithFlags(&s2, cudaStreamNonBlocking);
        cudaStreamCreateWithFlags(&s3, cudaStreamNonBlocking);
        cudaEventCreateWithFlags(&ev0, cudaEventDisableTiming);
        cudaEventCreateWithFlags(&evW, cudaEventDisableTiming);
        cudaEventCreateWithFlags(&evY1, cudaEventDisableTiming);
        cudaEventCreateWithFlags(&evG1, cudaEventDisableTiming);
        cudaEventCreateWithFlags(&evY2, cudaEventDisableTiming);
        cudaEventCreateWithFlags(&evG2, cudaEventDisableTiming);
        cudaFuncSetAttribute(tgemm_h<128, 0, 2, false>, cudaFuncAttributeMaxDynamicSharedMemorySize, SMEM_DYN);
        cudaFuncSetAttribute(tgemm_h<192, 1, 2, true>,  cudaFuncAttributeMaxDynamicSharedMemorySize, SMEM_DYN);
        cudaFuncSetAttribute(tgemm_h<192, 1, 0, true>,  cudaFuncAttributeMaxDynamicSharedMemorySize, SMEM_DYN);
        cudaFuncSetAttribute(tgemm_h<128, 1, 2, false>, cudaFuncAttributeMaxDynamicSharedMemorySize, SMEM_DYN);
        cudaFuncSetAttribute(tgemm_h<128, 1, 0, false>, cudaFuncAttributeMaxDynamicSharedMemorySize, SMEM_DYN);
        init_done = true;
    }

    const int GB = (NN + 127) / 128;
    cudaStream_t ms = 0;

    cudaEventRecord(ev0, ms);
    cudaStreamWaitEvent(s2, ev0, 0);
    cudaStreamWaitEvent(s3, ev0, 0);

    // s2: CSR build
    zero_cnt<<<(NN + 255) / 256, 256, 0, s2>>>();
    count_k<<<(E + 255) / 256, 256, 0, s2>>>(ei, E);
    scan_block<<<NB_SCAN, 1024, 0, s2>>>();
    scan_top<<<1, 32, 0, s2>>>();
    scan_add<<<(NN + 255) / 256, 256, 0, s2>>>();
    fill_k<<<(E + 255) / 256, 256, 0, s2>>>(ei, E);

    // s3: weight prep + folding + x_cont split (off the ms critical path)
    prep_weight<<<(128 * 128 + 255) / 256, 256, 0, s3>>>(W2, 128, wt + O_W2);
    fold_w3<<<64, 256, 0, s3>>>(W3, c1_Wl, b3, nullptr, wt + O_FL, p_bfl);
    fold_w3<<<64, 256, 0, s3>>>(W3, c1_Wr, b3, c1_bl,   wt + O_FR, p_bfr);
    prep_weight<<<(128 * 64 + 255) / 256, 256, 0, s3>>>(c1_Wl + 128 * 128, 64, wt + O_CL);
    prep_weight<<<(128 * 64 + 255) / 256, 256, 0, s3>>>(c1_Wr + 128 * 128, 64, wt + O_CR);
    prep_weight<<<(128 * 128 + 255) / 256, 256, 0, s3>>>(c2_Wl, 128, wt + O_C2L);
    prep_weight<<<(128 * 128 + 255) / 256, 256, 0, s3>>>(c2_Wr, 128, wt + O_C2R);
    copy_cont_h<<<(NN * 32 + 255) / 256, 256, 0, s3>>>(x_cont);
    cudaEventRecord(evW, s3);

    // ms: MLP layer 1 via fused fp16 tables
    prep_T<<<NCAT * 2, 256, 0, ms>>>(emb, W1);
    emb_mlp1<<<(NN * 32 + 255) / 256, 256, 0, ms>>>(x_cat, b1, p1);

    cudaStreamWaitEvent(ms, evW, 0);

    // MLP layer 2 (W3 folded into conv1)
    tgemm_h<128, 0, 2, false><<<GB, 256, SMEM_DYN, ms>>>(p1, 128, wt + O_W2, b2, p2, 128,
                                                         nullptr, nullptr);

    // ---- conv1: y = h2@Wfl + xc@Wlc + bfl (fp16); gather on s2; z = h2@Wfr + xc@Wrc + bfr
    tgemm_h<192, 1, 2, true><<<GB, 256, SMEM_DYN, ms>>>(p2, 128, wt + O_FL, p_bfl, p_y, 128,
                                                        p_c, wt + O_CL);
    cudaEventRecord(evY1, ms);
    cudaStreamWaitEvent(s2, evY1, 0);
    gather_vec<<<(NN * 32 + 255) / 256, 256, 0, s2>>>(p_y, p_agg);
    cudaEventRecord(evG1, s2);
    tgemm_h<192, 1, 0, true><<<GB, 256, SMEM_DYN, ms>>>(p2, 128, wt + O_FR, p_bfr, p_z, 128,
                                                        p_c, wt + O_CR);
    cudaStreamWaitEvent(ms, evG1, 0);
    ep_h<<<(NN * 32 + 255) / 256, 256, 0, ms>>>(p_z, p_agg, p1);

    // ---- conv2
    tgemm_h<128, 1, 2, false><<<GB, 256, SMEM_DYN, ms>>>(p1, 128, wt + O_C2L, nullptr, p_y, 128,
                                                         nullptr, nullptr);
    cudaEventRecord(evY2, ms);
    cudaStreamWaitEvent(s2, evY2, 0);
    gather_vec<<<(NN * 32 + 255) / 256, 256, 0, s2>>>(p_y, p_agg);
    cudaEventRecord(evG2, s2);
    tgemm_h<128, 1, 0, false><<<GB, 256, SMEM_DYN, ms>>>(p1, 128, wt + O_C2R, c2_bl, p_z, 128,
                                                         nullptr, nullptr);
    cudaStreamWaitEvent(ms, evG2, 0);

    // ---- conv2 epilogue fused with conv3 dots, then final gather
    ep2_conv3<<<(NN * 32 + 255) / 256, 256, 0, ms>>>(p_z, p_agg, c3_Wl, c3_Wr);
    gather3_final<<<(NN * 32 + 255) / 256, 256, 0, ms>>>(c3_bl, out);
}

// round 16
// speedup vs baseline: 1.1066x; 1.0334x over previous
#include <cuda_runtime.h>
#include <cuda_bf16.h>
#include <cuda_fp16.h>
#include <cstdint>
#include <math.h>

#define NN   100000
#define NE   1600000
#define NCAT 20
#define EMBD 32
#define CARD 100
#define NB_SCAN 98   // ceil(NN/1024)

// ---------------- scratch (device globals) ----------------
__device__ __half g_c[(size_t)NN * 64];           // x_cont fp16
__device__ __half g_p1[(size_t)NN * 128];         // layer buffers (fp16)
__device__ __half g_p2[(size_t)NN * 128];
__device__ __half g_y[(size_t)NN * 128];          // fp16 pre-aggregation features
__device__ float g_z[(size_t)NN * 128];
__device__ float g_agg[(size_t)NN * 128];
__device__ float g_s1[NN], g_s2[NN];
__device__ __half g_wt[768 * 128];                // [n][k] transposed fp16 weights
__device__ float g_bfl[128], g_bfr[128];          // folded conv1 biases
__device__ __half g_Th[NCAT * CARD * 128];        // fused emb@W1 tables (fp16)
// CSR
__device__ int g_cnt[NN];
__device__ int g_start[NN + 1];
__device__ int g_cursor[NN];
__device__ int g_csrc[NE];
__device__ int g_bsum[NB_SCAN];

__device__ __forceinline__ float gelu_f(float v) {
    return 0.5f * v * (1.0f + erff(v * 0.70710678118654752f));
}
__device__ __forceinline__ void mma_f16(float4& c, const uint32_t* a, const uint32_t* b) {
    asm volatile("mma.sync.aligned.m16n8k16.row.col.f32.f16.f16.f32 "
                 "{%0,%1,%2,%3}, {%4,%5,%6,%7}, {%8,%9}, {%0,%1,%2,%3};"
                 : "+f"(c.x), "+f"(c.y), "+f"(c.z), "+f"(c.w)
                 : "r"(a[0]), "r"(a[1]), "r"(a[2]), "r"(a[3]), "r"(b[0]), "r"(b[1]));
}
__device__ __forceinline__ void ldmx4(uint32_t& r0, uint32_t& r1, uint32_t& r2, uint32_t& r3,
                                      uint32_t addr) {
    asm volatile("ldmatrix.sync.aligned.m8n8.x4.shared.b16 {%0,%1,%2,%3}, [%4];"
                 : "=r"(r0), "=r"(r1), "=r"(r2), "=r"(r3) : "r"(addr));
}
__device__ __forceinline__ void cpasync16(uint32_t dst, const void* src) {
    asm volatile("cp.async.cg.shared.global [%0], [%1], 16;" :: "r"(dst), "l"(src));
}
__device__ __forceinline__ void cp_commit() { asm volatile("cp.async.commit_group;"); }
template<int N> __device__ __forceinline__ void cp_wait() {
    asm volatile("cp.async.wait_group %0;" :: "n"(N));
}

// ---------------- prep kernels ----------------
__global__ void prep_weight(const float* __restrict__ W, int K, __half* __restrict__ o) {
    int i = blockIdx.x * blockDim.x + threadIdx.x;
    if (i < 128 * K) {
        int k = i >> 7, n = i & 127;
        o[(size_t)n * K + k] = __float2half(W[i]);
    }
}
__global__ void __launch_bounds__(256)
fold_w3(const float* __restrict__ W3, const float* __restrict__ cW,
        const float* __restrict__ b3, const float* __restrict__ extra_bias,
        __half* __restrict__ o, float* __restrict__ obias) {
    int idx = blockIdx.x * 256 + threadIdx.x;
    int k = idx >> 7, n = idx & 127;
    float acc = 0.f;
    for (int d = 0; d < 128; d++)
        acc += W3[k * 128 + d] * cW[d * 128 + n];
    o[(size_t)n * 128 + k] = __float2half(acc);
    if (k == 0) {
        float bacc = extra_bias ? extra_bias[n] : 0.f;
        for (int d = 0; d < 128; d++) bacc += b3[d] * cW[d * 128 + n];
        obias[n] = bacc;
    }
}
__global__ void copy_cont_h(const float* __restrict__ xc) {
    int i = blockIdx.x * blockDim.x + threadIdx.x;
    if (i < NN * 32) {
        float2 v = *(const float2*)&xc[(size_t)i * 2];
        *(__half2*)&g_c[(size_t)i * 2] = __floats2half2_rn(v.x, v.y);
    }
}

// ---------------- emb@W1 table precompute (fp16 output) ----------------
__global__ void __launch_bounds__(256)
prep_T(const float* __restrict__ emb, const float* __restrict__ W1) {
    __shared__ float se[50 * 32];
    __shared__ float sw[32 * 128];
    int c = blockIdx.x >> 1;
    int rh = blockIdx.x & 1;
    int tid = threadIdx.x;
    for (int i = tid; i < 50 * 32; i += 256)
        se[i] = emb[(size_t)c * CARD * EMBD + rh * 50 * 32 + i];
    for (int i = tid; i < 32 * 128; i += 256)
        sw[i] = W1[(size_t)(c * 32) * 128 + i];
    __syncthreads();
    for (int i = 0; i < 25; i++) {
        int idx = tid + i * 256;
        int r = idx >> 7, n = idx & 127;
        float acc = 0.f;
#pragma unroll
        for (int d = 0; d < 32; d++)
            acc += se[r * 32 + d] * sw[d * 128 + n];
        g_Th[((size_t)c * CARD + rh * 50 + r) * 128 + n] = __float2half(acc);
    }
}

// ---------------- MLP layer 1 via fp16 table lookup-sum ----------------
__global__ void __launch_bounds__(256)
emb_mlp1(const int* __restrict__ xcat, const float* __restrict__ b1,
         __half* __restrict__ o) {
    int w = (blockIdx.x * blockDim.x + threadIdx.x) >> 5;
    if (w >= NN) return;
    int lane = threadIdx.x & 31;
    const int* xc = xcat + (size_t)w * NCAT;
    float4 acc = *(const float4*)&b1[lane * 4];
#pragma unroll
    for (int c = 0; c < NCAT; c++) {
        int cat = __ldg(&xc[c]);
        uint2 u = *(const uint2*)&g_Th[((size_t)c * CARD + cat) * 128 + lane * 4];
        float2 f0 = __half22float2(*(__half2*)&u.x);
        float2 f1 = __half22float2(*(__half2*)&u.y);
        acc.x += f0.x; acc.y += f0.y; acc.z += f1.x; acc.w += f1.y;
    }
    __half2 o0 = __floats2half2_rn(gelu_f(acc.x), gelu_f(acc.y));
    __half2 o1 = __floats2half2_rn(gelu_f(acc.z), gelu_f(acc.w));
    size_t off = (size_t)w * 128 + lane * 4;
    *(__half2*)&o[off] = o0;
    *(__half2*)&o[off + 2] = o1;
}

// ---------------- CSR build ----------------
__global__ void zero_cnt() {
    int i = blockIdx.x * blockDim.x + threadIdx.x;
    if (i < NN) g_cnt[i] = 0;
}
__global__ void count_k(const int* __restrict__ ei, int E) {
    int e = blockIdx.x * blockDim.x + threadIdx.x;
    if (e < E) atomicAdd(&g_cnt[ei[E + e]], 1);
}
__global__ void scan_block() {
    __shared__ int sh[1024];
    int tid = threadIdx.x;
    int i = blockIdx.x * 1024 + tid;
    int v = (i < NN) ? g_cnt[i] : 0;
    sh[tid] = v;
    __syncthreads();
#pragma unroll
    for (int off = 1; off < 1024; off <<= 1) {
        int t = (tid >= off) ? sh[tid - off] : 0;
        __syncthreads();
        sh[tid] += t;
        __syncthreads();
    }
    if (i < NN) g_start[i] = sh[tid] - v;
    if (tid == 1023) g_bsum[blockIdx.x] = sh[1023];
}
__global__ void scan_top() {
    if (threadIdx.x == 0) {
        int acc = 0;
        for (int j = 0; j < NB_SCAN; j++) { int t = g_bsum[j]; g_bsum[j] = acc; acc += t; }
        g_start[NN] = acc;
    }
}
__global__ void scan_add() {
    int i = blockIdx.x * blockDim.x + threadIdx.x;
    if (i < NN) {
        int s = g_start[i] + g_bsum[i >> 10];
        g_start[i] = s;
        g_cursor[i] = s;
    }
}
__global__ void fill_k(const int* __restrict__ ei, int E) {
    int e = blockIdx.x * blockDim.x + threadIdx.x;
    if (e < E) {
        int dst = ei[E + e];
        int pos = atomicAdd(&g_cursor[dst], 1);
        g_csrc[pos] = ei[e];
    }
}

// ---------------- gather kernels ----------------
__global__ void gather_vec(const __half* __restrict__ y, float* __restrict__ agg) {
    int w = (blockIdx.x * blockDim.x + threadIdx.x) >> 5;
    if (w >= NN) return;
    int lane = threadIdx.x & 31;
    int s = g_start[w], e = g_start[w + 1];
    float inv = 1.f / fmaxf((float)(e - s), 1.f);
    float a0 = 0.f, a1 = 0.f, a2 = 0.f, a3 = 0.f;
    float b0 = 0.f, b1 = 0.f, b2 = 0.f, b3 = 0.f;
    int i = s;
    for (; i + 1 < e; i += 2) {
        int r0 = g_csrc[i], r1 = g_csrc[i + 1];
        uint2 u0 = *(const uint2*)&y[(size_t)r0 * 128 + lane * 4];
        uint2 u1 = *(const uint2*)&y[(size_t)r1 * 128 + lane * 4];
        float2 p0 = __half22float2(*(__half2*)&u0.x);
        float2 p1 = __half22float2(*(__half2*)&u0.y);
        float2 q0 = __half22float2(*(__half2*)&u1.x);
        float2 q1 = __half22float2(*(__half2*)&u1.y);
        a0 += p0.x; a1 += p0.y; a2 += p1.x; a3 += p1.y;
        b0 += q0.x; b1 += q0.y; b2 += q1.x; b3 += q1.y;
    }
    if (i < e) {
        int r0 = g_csrc[i];
        uint2 u0 = *(const uint2*)&y[(size_t)r0 * 128 + lane * 4];
        float2 p0 = __half22float2(*(__half2*)&u0.x);
        float2 p1 = __half22float2(*(__half2*)&u0.y);
        a0 += p0.x; a1 += p0.y; a2 += p1.x; a3 += p1.y;
    }
    float4 o = make_float4((a0 + b0) * inv, (a1 + b1) * inv,
                           (a2 + b2) * inv, (a3 + b3) * inv);
    *(float4*)&agg[(size_t)w * 128 + lane * 4] = o;
}

__global__ void gather3_final(const float* __restrict__ bl, float* __restrict__ out) {
    int w = (blockIdx.x * blockDim.x + threadIdx.x) >> 5;
    if (w >= NN) return;
    int lane = threadIdx.x & 31;
    int s = g_start[w], e = g_start[w + 1];
    float inv = 1.f / fmaxf((float)(e - s), 1.f);
    float sum = 0.f;
    for (int i = s + lane; i < e; i += 32) sum += g_s1[g_csrc[i]];
#pragma unroll
    for (int o = 16; o > 0; o >>= 1) sum += __shfl_down_sync(0xffffffffu, sum, o);
    if (lane == 0) out[w] = sum * inv + bl[0] + g_s2[w];
}

// ---------------- epilogue conv1: v = gelu(z + agg) -> fp16 ----------------
__global__ void ep_h(const float* __restrict__ z, const float* __restrict__ agg,
                     __half* __restrict__ o) {
    int i = blockIdx.x * blockDim.x + threadIdx.x;
    if (i >= NN * 32) return;
    float4 zv = *(const float4*)&z[(size_t)i * 4];
    float4 av = *(const float4*)&agg[(size_t)i * 4];
    __half2 o0 = __floats2half2_rn(gelu_f(zv.x + av.x), gelu_f(zv.y + av.y));
    __half2 o1 = __floats2half2_rn(gelu_f(zv.z + av.z), gelu_f(zv.w + av.w));
    *(__half2*)&o[(size_t)i * 4] = o0;
    *(__half2*)&o[(size_t)i * 4 + 2] = o1;
}

// ---------------- epilogue conv2 fused with conv3 dots ----------------
__global__ void ep2_conv3(const float* __restrict__ z, const float* __restrict__ agg,
                          const float* __restrict__ Wl, const float* __restrict__ Wr) {
    int w = (blockIdx.x * blockDim.x + threadIdx.x) >> 5;
    if (w >= NN) return;
    int lane = threadIdx.x & 31;
    size_t o = (size_t)w * 128 + lane * 4;
    float4 zv = *(const float4*)&z[o];
    float4 av = *(const float4*)&agg[o];
    float h0 = gelu_f(zv.x + av.x), h1 = gelu_f(zv.y + av.y);
    float h2 = gelu_f(zv.z + av.z), h3 = gelu_f(zv.w + av.w);
    float4 wl = *(const float4*)&Wl[lane * 4];
    float4 wr = *(const float4*)&Wr[lane * 4];
    float s1 = h0 * wl.x + h1 * wl.y + h2 * wl.z + h3 * wl.w;
    float s2 = h0 * wr.x + h1 * wr.y + h2 * wr.z + h3 * wr.w;
#pragma unroll
    for (int off = 16; off > 0; off >>= 1) {
        s1 += __shfl_down_sync(0xffffffffu, s1, off);
        s2 += __shfl_down_sync(0xffffffffu, s2, off);
    }
    if (lane == 0) { g_s1[w] = s1; g_s2[w] = s2; }
}

// =====================================================================
// single-fp16 tensor GEMM with ldmatrix fragment loads
// SPLIT: k<128 from (A stride lda, B stride 128); k>=128 from (A2,B2; stride 64)
// EPI: 0 = gelu(v+bias); 1 = v+bias (bias may be null)
// OUTMODE: 0 = fp32 -> C0; 2 = fp16 -> C0
// =====================================================================
#define SMEM_DYN 32768

template<int K, int EPI, int OUTMODE, bool SPLIT>
__global__ void __launch_bounds__(256, 2)
tgemm_h(const __half* __restrict__ A, int lda,
        const __half* __restrict__ B,
        const float* __restrict__ bias,
        void* __restrict__ C0, int ldc,
        const __half* __restrict__ A2, const __half* __restrict__ B2)
{
    extern __shared__ __align__(16) char sm[];

    const int tid  = threadIdx.x;
    const int m0   = blockIdx.x * 128;
    const int wid  = tid >> 5;
    const int lane = tid & 31;
    const int g    = lane >> 2;
    const int tig  = lane & 3;
    const int warpM = (wid >> 2) * 64;
    const int warpN = (wid & 3) * 32;

    constexpr int NC = K / 32;
    constexpr int BK = SPLIT ? 128 : K;
    const uint32_t smB = (uint32_t)__cvta_generic_to_shared(sm);

    const int laneT8 = lane & 7;
    const int aRow   = laneT8 + ((lane >> 3) & 1) * 8;
    const int aKh    = lane >> 4;
    const int bNsel  = lane >> 4;
    const int bKh    = (lane >> 3) & 1;

    float4 acc[4][4];
#pragma unroll
    for (int i = 0; i < 4; i++)
#pragma unroll
        for (int j = 0; j < 4; j++) acc[i][j] = make_float4(0.f, 0.f, 0.f, 0.f);

    auto copy_tile = [&](int buf, int k0) {
        uint32_t st = smB + (uint32_t)buf * 16384;
#pragma unroll
        for (int i = 0; i < 2; i++) {
            int flat = tid + i * 256;
            int r = flat >> 2, seg = flat & 3;
            int row = m0 + r; if (row >= NN) row = NN - 1;
            const __half* src;
            if (SPLIT && k0 >= 128) {
                src = A2 + (size_t)row * 64 + (k0 - 128) + seg * 8;
            } else {
                src = A + (size_t)row * lda + k0 + seg * 8;
            }
            uint32_t dst = st + (uint32_t)r * 64
                         + (uint32_t)((seg ^ ((r >> 1) & 3)) << 4);
            cpasync16(dst, src);
        }
#pragma unroll
        for (int i = 0; i < 2; i++) {
            int flat = tid + i * 256;
            int n = flat >> 2, seg = flat & 3;
            const __half* src;
            if (SPLIT && k0 >= 128) {
                src = B2 + (size_t)n * 64 + (k0 - 128) + seg * 8;
            } else {
                src = B + (size_t)n * BK + k0 + seg * 8;
            }
            uint32_t dst = st + 8192u + (uint32_t)n * 64
                         + (uint32_t)((seg ^ ((n >> 1) & 3)) << 4);
            cpasync16(dst, src);
        }
        cp_commit();
    };

    copy_tile(0, 0);

    for (int ks = 0; ks < NC; ks++) {
        if (ks + 1 < NC) {
            copy_tile((ks + 1) & 1, (ks + 1) * 32);
            cp_wait<1>();
        } else {
            cp_wait<0>();
        }
        __syncthreads();

        const uint32_t stage = smB + (uint32_t)(ks & 1) * 16384;
        const uint32_t Abase = stage;
        const uint32_t Bbase = stage + 8192u;

#pragma unroll
        for (int kc = 0; kc < 2; kc++) {
            uint32_t bf[4][2];
#pragma unroll
            for (int p = 0; p < 2; p++) {
                int n = warpN + (p * 2 + bNsel) * 8 + laneT8;
                int seg = kc * 2 + bKh;
                uint32_t addr = Bbase + (uint32_t)n * 64
                              + (uint32_t)((seg ^ ((n >> 1) & 3)) << 4);
                ldmx4(bf[p * 2][0], bf[p * 2][1], bf[p * 2 + 1][0], bf[p * 2 + 1][1], addr);
            }
#pragma unroll
            for (int mt = 0; mt < 4; mt++) {
                int r = warpM + mt * 16 + aRow;
                int seg = kc * 2 + aKh;
                uint32_t addr = Abase + (uint32_t)r * 64
                              + (uint32_t)((seg ^ ((r >> 1) & 3)) << 4);
                uint32_t af[4];
                ldmx4(af[0], af[1], af[2], af[3], addr);
#pragma unroll
                for (int nt = 0; nt < 4; nt++)
                    mma_f16(acc[mt][nt], af, bf[nt]);
            }
        }
        __syncthreads();
    }

#pragma unroll
    for (int mt = 0; mt < 4; mt++) {
        int r0 = m0 + warpM + mt * 16 + g;
#pragma unroll
        for (int rr = 0; rr < 2; rr++) {
            int r = r0 + rr * 8;
            if (r >= NN) continue;
#pragma unroll
            for (int nt = 0; nt < 4; nt++) {
                int col = warpN + nt * 8 + tig * 2;
                float v0 = (rr == 0) ? acc[mt][nt].x : acc[mt][nt].z;
                float v1 = (rr == 0) ? acc[mt][nt].y : acc[mt][nt].w;
                if (bias) { v0 += bias[col]; v1 += bias[col + 1]; }
                if (EPI == 0) { v0 = gelu_f(v0); v1 = gelu_f(v1); }
                if (OUTMODE == 0) {
                    *(float2*)((float*)C0 + (size_t)r * ldc + col) = make_float2(v0, v1);
                } else {
                    *(__half2*)((__half*)C0 + (size_t)r * ldc + col) = __floats2half2_rn(v0, v1);
                }
            }
        }
    }
}

// ---------------- host ----------------
extern "C" void kernel_launch(void* const* d_in, const int* in_sizes, int n_in,
                              void* d_out, int out_size) {
    (void)n_in; (void)out_size;
    const int*   x_cat  = (const int*)  d_in[0];
    const float* x_cont = (const float*)d_in[1];
    const int*   ei     = (const int*)  d_in[2];
    const float* emb    = (const float*)d_in[3];
    const float* W1     = (const float*)d_in[4];
    const float* b1     = (const float*)d_in[5];
    const float* W2     = (const float*)d_in[6];
    const float* b2     = (const float*)d_in[7];
    const float* W3     = (const float*)d_in[8];
    const float* b3     = (const float*)d_in[9];
    const float* c1_Wl  = (const float*)d_in[10];
    const float* c1_bl  = (const float*)d_in[11];
    const float* c1_Wr  = (const float*)d_in[12];
    const float* c2_Wl  = (const float*)d_in[13];
    const float* c2_bl  = (const float*)d_in[14];
    const float* c2_Wr  = (const float*)d_in[15];
    const float* c3_Wl  = (const float*)d_in[16];
    const float* c3_bl  = (const float*)d_in[17];
    const float* c3_Wr  = (const float*)d_in[18];
    float* out = (float*)d_out;

    const int E = in_sizes[2] / 2;

    __half *p_c, *p1, *p2, *p_y, *wt;
    float *p_z, *p_agg, *p_bfl, *p_bfr;
    cudaGetSymbolAddress((void**)&p_c, g_c);
    cudaGetSymbolAddress((void**)&p1, g_p1);
    cudaGetSymbolAddress((void**)&p2, g_p2);
    cudaGetSymbolAddress((void**)&p_y, g_y);
    cudaGetSymbolAddress((void**)&p_z, g_z);
    cudaGetSymbolAddress((void**)&p_agg, g_agg);
    cudaGetSymbolAddress((void**)&wt, g_wt);
    cudaGetSymbolAddress((void**)&p_bfl, g_bfl);
    cudaGetSymbolAddress((void**)&p_bfr, g_bfr);

    const int O_W2  = 0;
    const int O_FL  = 16384;
    const int O_FR  = 32768;
    const int O_CL  = 49152;
    const int O_CR  = 57344;
    const int O_C2L = 65536;
    const int O_C2R = 81920;

    static cudaStream_t s2 = nullptr, s3 = nullptr;
    static cudaEvent_t ev0, evW, evY1, evG1, evY2, evG2;
    static bool init_done = false;
    if (!init_done) {
        cudaStreamCreateWithFlags(&s2, cudaStreamNonBlocking);
        cudaStreamCreateWithFlags(&s3, cudaStreamNonBlocking);
        cudaEventCreateWithFlags(&ev0, cudaEventDisableTiming);
        cudaEventCreateWithFlags(&evW, cudaEventDisableTiming);
        cudaEventCreateWithFlags(&evY1, cudaEventDisableTiming);
        cudaEventCreateWithFlags(&evG1, cudaEventDisableTiming);
        cudaEventCreateWithFlags(&evY2, cudaEventDisableTiming);
        cudaEventCreateWithFlags(&evG2, cudaEventDisableTiming);
        cudaFuncSetAttribute(tgemm_h<128, 0, 2, false>, cudaFuncAttributeMaxDynamicSharedMemorySize, SMEM_DYN);
        cudaFuncSetAttribute(tgemm_h<192, 1, 2, true>,  cudaFuncAttributeMaxDynamicSharedMemorySize, SMEM_DYN);
        cudaFuncSetAttribute(tgemm_h<192, 1, 0, true>,  cudaFuncAttributeMaxDynamicSharedMemorySize, SMEM_DYN);
        cudaFuncSetAttribute(tgemm_h<128, 1, 2, false>, cudaFuncAttributeMaxDynamicSharedMemorySize, SMEM_DYN);
        cudaFuncSetAttribute(tgemm_h<128, 1, 0, false>, cudaFuncAttributeMaxDynamicSharedMemorySize, SMEM_DYN);
        init_done = true;
    }

    const int GB = (NN + 127) / 128;
    cudaStream_t ms = 0;

    cudaEventRecord(ev0, ms);
    cudaStreamWaitEvent(s2, ev0, 0);
    cudaStreamWaitEvent(s3, ev0, 0);

    // s2: CSR build
    zero_cnt<<<(NN + 255) / 256, 256, 0, s2>>>();
    count_k<<<(E + 255) / 256, 256, 0, s2>>>(ei, E);
    scan_block<<<NB_SCAN, 1024, 0, s2>>>();
    scan_top<<<1, 32, 0, s2>>>();
    scan_add<<<(NN + 255) / 256, 256, 0, s2>>>();
    fill_k<<<(E + 255) / 256, 256, 0, s2>>>(ei, E);

    // s3: weight prep + folding
    prep_weight<<<(128 * 128 + 255) / 256, 256, 0, s3>>>(W2, 128, wt + O_W2);
    fold_w3<<<64, 256, 0, s3>>>(W3, c1_Wl, b3, nullptr, wt + O_FL, p_bfl);
    fold_w3<<<64, 256, 0, s3>>>(W3, c1_Wr, b3, c1_bl,   wt + O_FR, p_bfr);
    prep_weight<<<(128 * 64 + 255) / 256, 256, 0, s3>>>(c1_Wl + 128 * 128, 64, wt + O_CL);
    prep_weight<<<(128 * 64 + 255) / 256, 256, 0, s3>>>(c1_Wr + 128 * 128, 64, wt + O_CR);
    prep_weight<<<(128 * 128 + 255) / 256, 256, 0, s3>>>(c2_Wl, 128, wt + O_C2L);
    prep_weight<<<(128 * 128 + 255) / 256, 256, 0, s3>>>(c2_Wr, 128, wt + O_C2R);
    cudaEventRecord(evW, s3);

    // ms: MLP layer 1 via fused fp16 tables
    prep_T<<<NCAT * 2, 256, 0, ms>>>(emb, W1);
    copy_cont_h<<<(NN * 32 + 255) / 256, 256, 0, ms>>>(x_cont);
    emb_mlp1<<<(NN * 32 + 255) / 256, 256, 0, ms>>>(x_cat, b1, p1);

    cudaStreamWaitEvent(ms, evW, 0);

    // MLP layer 2 (W3 folded into conv1)
    tgemm_h<128, 0, 2, false><<<GB, 256, SMEM_DYN, ms>>>(p1, 128, wt + O_W2, b2, p2, 128,
                                                         nullptr, nullptr);

    // ---- conv1: y = h2@Wfl + xc@Wlc + bfl (fp16); gather on s2; z = h2@Wfr + xc@Wrc + bfr
    tgemm_h<192, 1, 2, true><<<GB, 256, SMEM_DYN, ms>>>(p2, 128, wt + O_FL, p_bfl, p_y, 128,
                                                        p_c, wt + O_CL);
    cudaEventRecord(evY1, ms);
    cudaStreamWaitEvent(s2, evY1, 0);
    gather_vec<<<(NN * 32 + 255) / 256, 256, 0, s2>>>(p_y, p_agg);
    cudaEventRecord(evG1, s2);
    tgemm_h<192, 1, 0, true><<<GB, 256, SMEM_DYN, ms>>>(p2, 128, wt + O_FR, p_bfr, p_z, 128,
                                                        p_c, wt + O_CR);
    cudaStreamWaitEvent(ms, evG1, 0);
    ep_h<<<(NN * 32 + 255) / 256, 256, 0, ms>>>(p_z, p_agg, p1);

    // ---- conv2
    tgemm_h<128, 1, 2, false><<<GB, 256, SMEM_DYN, ms>>>(p1, 128, wt + O_C2L, nullptr, p_y, 128,
                                                         nullptr, nullptr);
    cudaEventRecord(evY2, ms);
    cudaStreamWaitEvent(s2, evY2, 0);
    gather_vec<<<(NN * 32 + 255) / 256, 256, 0, s2>>>(p_y, p_agg);
    cudaEventRecord(evG2, s2);
    tgemm_h<128, 1, 0, false><<<GB, 256, SMEM_DYN, ms>>>(p1, 128, wt + O_C2R, c2_bl, p_z, 128,
                                                         nullptr, nullptr);
    cudaStreamWaitEvent(ms, evG2, 0);

    // ---- conv2 epilogue fused with conv3 dots, then final gather
    ep2_conv3<<<(NN * 32 + 255) / 256, 256, 0, ms>>>(p_z, p_agg, c3_Wl, c3_Wr);
    gather3_final<<<(NN * 32 + 255) / 256, 256, 0, ms>>>(c3_bl, out);
}